// round 1
// baseline (speedup 1.0000x reference)
#include <cuda_runtime.h>
#include <math.h>

// ---------------------------------------------------------------------------
// Problem constants (fixed by the dataset): N=100000 nodes, E=1600000 edges,
// feature dims 256 -> 128 -> 128.
// ---------------------------------------------------------------------------
#define NMAX 100000
#define EMAX 1600000
#define FDIM 128

// Scratch (static device globals; no runtime allocation).
__device__ float g_deg [NMAX];
__device__ float g_dinv[NMAX];
__device__ float g_coef[EMAX];
__device__ float g_h   [(size_t)NMAX * FDIM];  // GEMM output (pre-aggregation)
__device__ float g_a   [(size_t)NMAX * FDIM];  // layer-1 aggregated / activated

// ---------------------------------------------------------------------------
// Degree / normalization
// ---------------------------------------------------------------------------
__global__ void k_init_deg(float* deg, int n) {
    int i = blockIdx.x * blockDim.x + threadIdx.x;
    if (i < n) deg[i] = 1.0f;  // self-loop weight
}

__global__ void k_deg_atomic(const int* __restrict__ dst,
                             const float* __restrict__ w,
                             float* deg, int E) {
    int e = blockIdx.x * blockDim.x + threadIdx.x;
    if (e < E) atomicAdd(&deg[dst[e]], w[e]);
}

__global__ void k_dinv(const float* __restrict__ deg, float* dinv, int n) {
    int i = blockIdx.x * blockDim.x + threadIdx.x;
    if (i < n) dinv[i] = rsqrtf(deg[i]);  // deg >= 1 always (self loop)
}

__global__ void k_coef(const int* __restrict__ src, const int* __restrict__ dst,
                       const float* __restrict__ w, const float* __restrict__ dinv,
                       float* coef, int E) {
    int e = blockIdx.x * blockDim.x + threadIdx.x;
    if (e < E) coef[e] = dinv[src[e]] * w[e] * dinv[dst[e]];
}

// ---------------------------------------------------------------------------
// SGEMM: C[M,128] = A[M,K] * B[K,128], fp32.
// Block tile 128x128, K-tile 16, 256 threads, 8x8 per-thread microtile,
// global->register prefetch overlapping the FMA phase.
// Requires K % 16 == 0 (K is 256 or 128 here).
// ---------------------------------------------------------------------------
__global__ __launch_bounds__(256, 2)
void k_sgemm128(const float* __restrict__ A, const float* __restrict__ B,
                float* __restrict__ C, int M, int K) {
    __shared__ float As[16][128];   // transposed: As[k][m]
    __shared__ float Bs[16][128];   // Bs[k][n]

    const int tid = threadIdx.x;
    const int m0  = blockIdx.x * 128;
    const int tx  = tid & 15;       // n-group
    const int ty  = tid >> 4;       // m-group

    float acc[8][8];
#pragma unroll
    for (int i = 0; i < 8; i++)
#pragma unroll
        for (int j = 0; j < 8; j++) acc[i][j] = 0.0f;

    float4 pa[2], pb[2];

    // prefetch tile at k0 into registers
    auto load_tiles = [&](int k0) {
#pragma unroll
        for (int u = 0; u < 2; u++) {
            int idx = tid + u * 256;          // 0..511
            int row = idx >> 2;               // 0..127
            int kq  = idx & 3;                // 0..3  (float4 along K)
            int gr  = m0 + row;
            if (gr < M)
                pa[u] = *(const float4*)(A + (size_t)gr * K + k0 + kq * 4);
            else
                pa[u] = make_float4(0.f, 0.f, 0.f, 0.f);

            int brow = idx >> 5;              // 0..15
            int c4   = idx & 31;              // 0..31
            pb[u] = *(const float4*)(B + (size_t)(k0 + brow) * 128 + c4 * 4);
        }
    };

    auto store_smem = [&]() {
#pragma unroll
        for (int u = 0; u < 2; u++) {
            int idx = tid + u * 256;
            int row = idx >> 2;
            int kq  = idx & 3;
            As[kq * 4 + 0][row] = pa[u].x;
            As[kq * 4 + 1][row] = pa[u].y;
            As[kq * 4 + 2][row] = pa[u].z;
            As[kq * 4 + 3][row] = pa[u].w;
            int brow = idx >> 5;
            int c4   = idx & 31;
            *(float4*)&Bs[brow][c4 * 4] = pb[u];
        }
    };

    load_tiles(0);

    for (int k0 = 0; k0 < K; k0 += 16) {
        __syncthreads();
        store_smem();
        __syncthreads();
        if (k0 + 16 < K) load_tiles(k0 + 16);

#pragma unroll
        for (int kk = 0; kk < 16; kk++) {
            float a[8], b[8];
            *(float4*)&a[0] = *(const float4*)&As[kk][ty * 8];
            *(float4*)&a[4] = *(const float4*)&As[kk][ty * 8 + 4];
            *(float4*)&b[0] = *(const float4*)&Bs[kk][tx * 8];
            *(float4*)&b[4] = *(const float4*)&Bs[kk][tx * 8 + 4];
#pragma unroll
            for (int i = 0; i < 8; i++)
#pragma unroll
                for (int j = 0; j < 8; j++)
                    acc[i][j] = fmaf(a[i], b[j], acc[i][j]);
        }
    }

#pragma unroll
    for (int i = 0; i < 8; i++) {
        int row = m0 + ty * 8 + i;
        if (row < M) {
            float4 v0 = make_float4(acc[i][0], acc[i][1], acc[i][2], acc[i][3]);
            float4 v1 = make_float4(acc[i][4], acc[i][5], acc[i][6], acc[i][7]);
            *(float4*)(C + (size_t)row * 128 + tx * 8)     = v0;
            *(float4*)(C + (size_t)row * 128 + tx * 8 + 4) = v1;
        }
    }
}

// ---------------------------------------------------------------------------
// Self-loop init: out[i,:] = h[i,:] * dinv[i]^2   (also initializes out)
// One thread per float4 -> 32 threads per node row.
// ---------------------------------------------------------------------------
__global__ void k_selfinit(const float* __restrict__ h,
                           const float* __restrict__ dinv,
                           float* __restrict__ out, int n) {
    int idx = blockIdx.x * blockDim.x + threadIdx.x;   // over n*32 float4s
    if (idx < n * 32) {
        int i = idx >> 5;
        float d = dinv[i];
        float c = d * d;
        float4 v = ((const float4*)h)[idx];
        v.x *= c; v.y *= c; v.z *= c; v.w *= c;
        ((float4*)out)[idx] = v;
    }
}

// ---------------------------------------------------------------------------
// Edge scatter: out[dst] += h[src] * coef, one warp per edge.
// float4 gather + vectorized red.global.add.v4.f32 (4x fewer L2 atomic ops).
// ---------------------------------------------------------------------------
__global__ void k_scatter(const int* __restrict__ src,
                          const int* __restrict__ dst,
                          const float* __restrict__ coef,
                          const float* __restrict__ h,
                          float* __restrict__ out, int E) {
    int warp = (blockIdx.x * blockDim.x + threadIdx.x) >> 5;
    int lane = threadIdx.x & 31;
    if (warp >= E) return;
    int   s = __ldg(&src[warp]);
    int   d = __ldg(&dst[warp]);
    float c = __ldg(&coef[warp]);
    float4 v = ((const float4*)(h + (size_t)s * 128))[lane];
    float* p = out + (size_t)d * 128 + lane * 4;
    asm volatile("red.global.add.v4.f32 [%0], {%1,%2,%3,%4};"
                 :: "l"(p), "f"(v.x * c), "f"(v.y * c), "f"(v.z * c), "f"(v.w * c)
                 : "memory");
}

// ---------------------------------------------------------------------------
// Bias + exact GELU (erf), in place. One thread per float4.
// ---------------------------------------------------------------------------
__device__ __forceinline__ float gelu_erf(float x) {
    return 0.5f * x * (1.0f + erff(x * 0.70710678118654752440f));
}

__global__ void k_bias_gelu(float* __restrict__ x, const float* __restrict__ b, int n) {
    int idx = blockIdx.x * blockDim.x + threadIdx.x;   // over n*32 float4s
    if (idx < n * 32) {
        int c4 = (idx & 31) * 4;
        float4 bb = *(const float4*)(b + c4);
        float4 v = ((float4*)x)[idx];
        v.x = gelu_erf(v.x + bb.x);
        v.y = gelu_erf(v.y + bb.y);
        v.z = gelu_erf(v.z + bb.z);
        v.w = gelu_erf(v.w + bb.w);
        ((float4*)x)[idx] = v;
    }
}

// ---------------------------------------------------------------------------
// Launch
// ---------------------------------------------------------------------------
extern "C" void kernel_launch(void* const* d_in, const int* in_sizes, int n_in,
                              void* d_out, int out_size) {
    const float* x  = (const float*)d_in[0];
    const int*   ei = (const int*)  d_in[1];
    const float* ew = (const float*)d_in[2];
    const float* W1 = (const float*)d_in[3];
    const float* b1 = (const float*)d_in[4];
    const float* W2 = (const float*)d_in[5];
    const float* b2 = (const float*)d_in[6];
    float* out = (float*)d_out;

    const int n  = out_size / FDIM;       // 100000
    const int K1 = in_sizes[0] / n;       // 256
    const int E  = in_sizes[2];           // 1600000
    const int*   src = ei;
    const int*   dst = ei + E;

    // resolve scratch symbol addresses (host-side query; capture-safe)
    float *deg, *dinv, *coef, *h, *a;
    cudaGetSymbolAddress((void**)&deg,  g_deg);
    cudaGetSymbolAddress((void**)&dinv, g_dinv);
    cudaGetSymbolAddress((void**)&coef, g_coef);
    cudaGetSymbolAddress((void**)&h,    g_h);
    cudaGetSymbolAddress((void**)&a,    g_a);

    const int TB = 256;
    dim3 gn((n + TB - 1) / TB);
    dim3 ge((E + TB - 1) / TB);
    dim3 gvec((n * 32 + TB - 1) / TB);         // n*32 float4s
    dim3 gscat((E + 7) / 8);                   // one warp per edge, 8 warps/block
    dim3 ggemm((n + 127) / 128);

    // --- normalization coefficients (shared by both layers) ---
    k_init_deg  <<<gn, TB>>>(deg, n);
    k_deg_atomic<<<ge, TB>>>(dst, ew, deg, E);
    k_dinv      <<<gn, TB>>>(deg, dinv, n);
    k_coef      <<<ge, TB>>>(src, dst, ew, dinv, coef, E);

    // --- layer 1: h = x @ W1 ; a = scatter(h) ; a = gelu(a + b1) ---
    k_sgemm128 <<<ggemm, TB>>>(x, W1, h, n, K1);
    k_selfinit <<<gvec, TB>>>(h, dinv, a, n);
    k_scatter  <<<gscat, TB>>>(src, dst, coef, h, a, E);
    k_bias_gelu<<<gvec, TB>>>(a, b1, n);

    // --- layer 2: h = a @ W2 ; out = scatter(h) ; out = gelu(out + b2) ---
    k_sgemm128 <<<ggemm, TB>>>(a, W2, h, n, FDIM);
    k_selfinit <<<gvec, TB>>>(h, dinv, out, n);
    k_scatter  <<<gscat, TB>>>(src, dst, coef, h, out, E);
    k_bias_gelu<<<gvec, TB>>>(out, b2, n);
}

// round 3
// speedup vs baseline: 1.3671x; 1.3671x over previous
#include <cuda_runtime.h>
#include <math.h>
#include <stdint.h>

// ---------------------------------------------------------------------------
// Problem constants: N=100000 nodes, E=1600000 edges, dims 256 -> 128 -> 128.
// ---------------------------------------------------------------------------
#define NMAX 100000
#define EMAX 1600000
#define FDIM 128

// Scratch (static device globals; no runtime allocation).
__device__ float g_deg [NMAX];
__device__ float g_dinv[NMAX];
__device__ float g_coef[EMAX];
__device__ float g_h   [(size_t)NMAX * FDIM];   // GEMM output (pre-aggregation)
__device__ float g_a   [(size_t)NMAX * FDIM];   // layer-1 aggregated / activated

// ---------------------------------------------------------------------------
// Degree / normalization
// ---------------------------------------------------------------------------
__global__ void k_init_deg(float* deg, int n) {
    int i = blockIdx.x * blockDim.x + threadIdx.x;
    if (i < n) deg[i] = 1.0f;
}

__global__ void k_deg_atomic(const int* __restrict__ dst, const float* __restrict__ w,
                             float* deg, int E) {
    int e = blockIdx.x * blockDim.x + threadIdx.x;
    if (e < E) atomicAdd(&deg[dst[e]], w[e]);
}

__global__ void k_dinv(const float* __restrict__ deg, float* dinv, int n) {
    int i = blockIdx.x * blockDim.x + threadIdx.x;
    if (i < n) dinv[i] = rsqrtf(deg[i]);
}

__global__ void k_coef(const int* __restrict__ src, const int* __restrict__ dst,
                       const float* __restrict__ w, const float* __restrict__ dinv,
                       float* coef, int E) {
    int e = blockIdx.x * blockDim.x + threadIdx.x;
    if (e < E) coef[e] = dinv[src[e]] * w[e] * dinv[dst[e]];
}

// ---------------------------------------------------------------------------
// tf32 mma.sync GEMM: C[M,128] = A[M,K] @ B[K,128]   (B = weight, used as-is)
// CTA tile 128x128, BK=16, 256 threads = 8 warps (4x2), warp tile 32x64,
// mma.m16n8k8.tf32, fp32 accumulate. Double-buffered SMEM, reg prefetch.
// Epilogue also writes Oinit = C * dinv[row]^2 (fused self-loop init).
// ---------------------------------------------------------------------------
#define APITCH 20     // floats per A smem row [m][k], bank-conflict-free frags
#define BPITCH 136    // floats per B smem row [k][n]

__device__ __forceinline__ uint32_t f2tf32(float x) {
    uint32_t r;
    asm("cvt.rna.tf32.f32 %0, %1;" : "=r"(r) : "f"(x));
    return r;
}

__device__ __forceinline__ void mma_tf32(float* c, const uint32_t* a,
                                         uint32_t b0, uint32_t b1) {
    asm volatile(
        "mma.sync.aligned.m16n8k8.row.col.f32.tf32.tf32.f32 "
        "{%0,%1,%2,%3}, {%4,%5,%6,%7}, {%8,%9}, {%0,%1,%2,%3};"
        : "+f"(c[0]), "+f"(c[1]), "+f"(c[2]), "+f"(c[3])
        : "r"(a[0]), "r"(a[1]), "r"(a[2]), "r"(a[3]), "r"(b0), "r"(b1));
}

__global__ __launch_bounds__(256, 2)
void k_gemm_mma(const float* __restrict__ A, const float* __restrict__ B,
                float* __restrict__ C, const float* __restrict__ dinv,
                float* __restrict__ Oinit, int M, int K) {
    __shared__ __align__(16) float As[2][128 * APITCH];
    __shared__ __align__(16) float Bs[2][16 * BPITCH];

    const int tid  = threadIdx.x;
    const int lane = tid & 31;
    const int wid  = tid >> 5;
    const int warp_m = wid & 3;    // 4 warps over M (32 rows each)
    const int warp_n = wid >> 2;   // 2 warps over N (64 cols each)
    const int gp = lane >> 2;      // group id 0..7
    const int tg = lane & 3;       // thread-in-group 0..3
    const int m0 = blockIdx.x * 128;

    float acc[2][8][4];
#pragma unroll
    for (int i = 0; i < 2; i++)
#pragma unroll
        for (int j = 0; j < 8; j++)
#pragma unroll
            for (int q = 0; q < 4; q++) acc[i][j][q] = 0.0f;

    float4 pa[2], pb[2];

    auto load_regs = [&](int k0) {
#pragma unroll
        for (int u = 0; u < 2; u++) {
            int idx = tid + u * 256;            // 0..511
            int ar  = idx >> 2;                 // A row 0..127
            int aq  = idx & 3;                  // float4 along K
            pa[u] = (m0 + ar < M)
                  ? *(const float4*)(A + (size_t)(m0 + ar) * K + k0 + aq * 4)
                  : make_float4(0.f, 0.f, 0.f, 0.f);
            int kr = idx >> 5;                  // B k-row 0..15
            int bq = idx & 31;                  // float4 along N
            pb[u] = *(const float4*)(B + (size_t)(k0 + kr) * 128 + bq * 4);
        }
    };

    auto store_smem = [&](int buf) {
#pragma unroll
        for (int u = 0; u < 2; u++) {
            int idx = tid + u * 256;
            int ar  = idx >> 2;
            int aq  = idx & 3;
            uint32_t* d = (uint32_t*)&As[buf][ar * APITCH + aq * 4];
            d[0] = f2tf32(pa[u].x); d[1] = f2tf32(pa[u].y);
            d[2] = f2tf32(pa[u].z); d[3] = f2tf32(pa[u].w);
            int kr = idx >> 5;
            int bq = idx & 31;
            uint32_t* e = (uint32_t*)&Bs[buf][kr * BPITCH + bq * 4];
            e[0] = f2tf32(pb[u].x); e[1] = f2tf32(pb[u].y);
            e[2] = f2tf32(pb[u].z); e[3] = f2tf32(pb[u].w);
        }
    };

    const int niter = K / 16;
    load_regs(0);
    store_smem(0);

    for (int it = 0; it < niter; it++) {
        if (it + 1 < niter) load_regs((it + 1) * 16);
        __syncthreads();
        const int buf = it & 1;
        const uint32_t* as = (const uint32_t*)&As[buf][0];
        const uint32_t* bs = (const uint32_t*)&Bs[buf][0];

#pragma unroll
        for (int kk = 0; kk < 16; kk += 8) {
            uint32_t af[2][4];
#pragma unroll
            for (int i = 0; i < 2; i++) {
                int mr = warp_m * 32 + i * 16 + gp;
                af[i][0] = as[(mr    ) * APITCH + kk + tg    ];
                af[i][1] = as[(mr + 8) * APITCH + kk + tg    ];
                af[i][2] = as[(mr    ) * APITCH + kk + tg + 4];
                af[i][3] = as[(mr + 8) * APITCH + kk + tg + 4];
            }
#pragma unroll
            for (int j = 0; j < 8; j++) {
                int nb = warp_n * 64 + j * 8 + gp;
                uint32_t b0 = bs[(kk + tg    ) * BPITCH + nb];
                uint32_t b1 = bs[(kk + tg + 4) * BPITCH + nb];
#pragma unroll
                for (int i = 0; i < 2; i++)
                    mma_tf32(acc[i][j], af[i], b0, b1);
            }
        }
        if (it + 1 < niter) store_smem((it + 1) & 1);
    }

    // epilogue: write C and Oinit = C * dinv^2 (fused self-loop term)
#pragma unroll
    for (int i = 0; i < 2; i++) {
        int r0 = m0 + warp_m * 32 + i * 16 + gp;
        int r1 = r0 + 8;
        float d0 = 0.f, d1 = 0.f;
        if (r0 < M) { d0 = dinv[r0]; d0 *= d0; }
        if (r1 < M) { d1 = dinv[r1]; d1 *= d1; }
#pragma unroll
        for (int j = 0; j < 8; j++) {
            int col = warp_n * 64 + j * 8 + tg * 2;
            if (r0 < M) {
                float2 v = make_float2(acc[i][j][0], acc[i][j][1]);
                *(float2*)(C     + (size_t)r0 * 128 + col) = v;
                *(float2*)(Oinit + (size_t)r0 * 128 + col) = make_float2(v.x * d0, v.y * d0);
            }
            if (r1 < M) {
                float2 v = make_float2(acc[i][j][2], acc[i][j][3]);
                *(float2*)(C     + (size_t)r1 * 128 + col) = v;
                *(float2*)(Oinit + (size_t)r1 * 128 + col) = make_float2(v.x * d1, v.y * d1);
            }
        }
    }
}

// ---------------------------------------------------------------------------
// Edge scatter: out[dst] += h[src] * coef, one warp per edge, v4 red.
// ---------------------------------------------------------------------------
__global__ void k_scatter(const int* __restrict__ src, const int* __restrict__ dst,
                          const float* __restrict__ coef, const float* __restrict__ h,
                          float* __restrict__ out, int E) {
    int warp = (blockIdx.x * blockDim.x + threadIdx.x) >> 5;
    int lane = threadIdx.x & 31;
    if (warp >= E) return;
    int   s = __ldg(&src[warp]);
    int   d = __ldg(&dst[warp]);
    float c = __ldg(&coef[warp]);
    float4 v = ((const float4*)(h + (size_t)s * 128))[lane];
    float* p = out + (size_t)d * 128 + lane * 4;
    asm volatile("red.global.add.v4.f32 [%0], {%1,%2,%3,%4};"
                 :: "l"(p), "f"(v.x * c), "f"(v.y * c), "f"(v.z * c), "f"(v.w * c)
                 : "memory");
}

// ---------------------------------------------------------------------------
// Bias + exact GELU (erf), in place.
// ---------------------------------------------------------------------------
__device__ __forceinline__ float gelu_erf(float x) {
    return 0.5f * x * (1.0f + erff(x * 0.70710678118654752440f));
}

__global__ void k_bias_gelu(float* __restrict__ x, const float* __restrict__ b, int n) {
    int idx = blockIdx.x * blockDim.x + threadIdx.x;
    if (idx < n * 32) {
        int c4 = (idx & 31) * 4;
        float4 bb = *(const float4*)(b + c4);
        float4 v = ((float4*)x)[idx];
        v.x = gelu_erf(v.x + bb.x);
        v.y = gelu_erf(v.y + bb.y);
        v.z = gelu_erf(v.z + bb.z);
        v.w = gelu_erf(v.w + bb.w);
        ((float4*)x)[idx] = v;
    }
}

// ---------------------------------------------------------------------------
// Launch
// ---------------------------------------------------------------------------
extern "C" void kernel_launch(void* const* d_in, const int* in_sizes, int n_in,
                              void* d_out, int out_size) {
    const float* x  = (const float*)d_in[0];
    const int*   ei = (const int*)  d_in[1];
    const float* ew = (const float*)d_in[2];
    const float* W1 = (const float*)d_in[3];
    const float* b1 = (const float*)d_in[4];
    const float* W2 = (const float*)d_in[5];
    const float* b2 = (const float*)d_in[6];
    float* out = (float*)d_out;

    const int n  = out_size / FDIM;       // 100000
    const int K1 = in_sizes[0] / n;       // 256
    const int E  = in_sizes[2];           // 1600000
    const int* src = ei;
    const int* dst = ei + E;

    float *deg, *dinv, *coef, *h, *a;
    cudaGetSymbolAddress((void**)&deg,  g_deg);
    cudaGetSymbolAddress((void**)&dinv, g_dinv);
    cudaGetSymbolAddress((void**)&coef, g_coef);
    cudaGetSymbolAddress((void**)&h,    g_h);
    cudaGetSymbolAddress((void**)&a,    g_a);

    const int TB = 256;
    dim3 gn((n + TB - 1) / TB);
    dim3 ge((E + TB - 1) / TB);
    dim3 gvec((n * 32 + TB - 1) / TB);
    dim3 gscat((E + 7) / 8);
    dim3 ggemm((n + 127) / 128);

    // --- normalization coefficients (shared by both layers) ---
    k_init_deg  <<<gn, TB>>>(deg, n);
    k_deg_atomic<<<ge, TB>>>(dst, ew, deg, E);
    k_dinv      <<<gn, TB>>>(deg, dinv, n);
    k_coef      <<<ge, TB>>>(src, dst, ew, dinv, coef, E);

    // --- layer 1: h = x@W1 (epilogue seeds a = h*dinv^2); scatter; gelu ---
    k_gemm_mma <<<ggemm, 256>>>(x, W1, h, dinv, a, n, K1);
    k_scatter  <<<gscat, TB>>>(src, dst, coef, h, a, E);
    k_bias_gelu<<<gvec, TB>>>(a, b1, n);

    // --- layer 2 ---
    k_gemm_mma <<<ggemm, 256>>>(a, W2, h, dinv, out, n, FDIM);
    k_scatter  <<<gscat, TB>>>(src, dst, coef, h, out, E);
    k_bias_gelu<<<gvec, TB>>>(out, b2, n);
}

// round 4
// speedup vs baseline: 2.2226x; 1.6258x over previous
#include <cuda_runtime.h>
#include <math.h>
#include <stdint.h>

// ---------------------------------------------------------------------------
// Problem constants: N=100000 nodes, E=1600000 edges, dims 256 -> 128 -> 128.
// ---------------------------------------------------------------------------
#define NMAX 100000
#define EMAX 1600000
#define FDIM 128

// Scratch (static device globals; no runtime allocation).
__device__ float g_deg   [NMAX];
__device__ float g_dinv  [NMAX];
__device__ int   g_cnt   [NMAX];
__device__ int   g_rowptr[NMAX + 1];
__device__ int   g_cursor[NMAX];
__device__ int   g_srcs  [EMAX];     // CSR-by-dst: source node per slot
__device__ float g_coefs [EMAX];     // CSR-by-dst: edge coefficient per slot
__device__ float g_h     [(size_t)NMAX * FDIM];  // GEMM output
__device__ float g_a     [(size_t)NMAX * FDIM];  // layer-1 activation

// ---------------------------------------------------------------------------
// Degree / counts
// ---------------------------------------------------------------------------
__global__ void k_init(float* deg, int* cnt, int n) {
    int i = blockIdx.x * blockDim.x + threadIdx.x;
    if (i < n) { deg[i] = 1.0f; cnt[i] = 0; }
}

__global__ void k_deg_cnt(const int* __restrict__ dst, const float* __restrict__ w,
                          float* deg, int* cnt, int E) {
    int e = blockIdx.x * blockDim.x + threadIdx.x;
    if (e < E) {
        int d = dst[e];
        atomicAdd(&deg[d], w[e]);
        atomicAdd(&cnt[d], 1);
    }
}

__global__ void k_dinv(const float* __restrict__ deg, float* dinv, int n) {
    int i = blockIdx.x * blockDim.x + threadIdx.x;
    if (i < n) dinv[i] = rsqrtf(deg[i]);
}

// ---------------------------------------------------------------------------
// Single-block exclusive scan over cnt -> rowptr (n up to 100k, 1024 threads).
// ---------------------------------------------------------------------------
__global__ void k_scan(const int* __restrict__ cnt, int* __restrict__ rowptr,
                       int n, int E) {
    __shared__ int wsum[32];
    __shared__ int carry_s;
    const int tid = threadIdx.x, lane = tid & 31, wid = tid >> 5;
    if (tid == 0) carry_s = 0;
    __syncthreads();
    for (int base = 0; base < n; base += 1024) {
        int i = base + tid;
        int v = (i < n) ? cnt[i] : 0;
        int x = v;
#pragma unroll
        for (int d = 1; d < 32; d <<= 1) {
            int y = __shfl_up_sync(0xffffffffu, x, d);
            if (lane >= d) x += y;
        }
        if (lane == 31) wsum[wid] = x;
        __syncthreads();
        if (wid == 0) {
            int s = wsum[lane];
#pragma unroll
            for (int d = 1; d < 32; d <<= 1) {
                int y = __shfl_up_sync(0xffffffffu, s, d);
                if (lane >= d) s += y;
            }
            wsum[lane] = s;
        }
        __syncthreads();
        int carry = carry_s;
        int woff  = wid ? wsum[wid - 1] : 0;
        if (i < n) rowptr[i] = carry + woff + x - v;
        __syncthreads();
        if (tid == 0) carry_s = carry + wsum[31];
        __syncthreads();
    }
    if (tid == 0) rowptr[n] = E;
}

__global__ void k_copy(const int* __restrict__ a, int* __restrict__ b, int n) {
    int i = blockIdx.x * blockDim.x + threadIdx.x;
    if (i < n) b[i] = a[i];
}

// Fill CSR slots; also computes the per-edge GCN coefficient.
__global__ void k_fill(const int* __restrict__ src, const int* __restrict__ dst,
                       const float* __restrict__ w, const float* __restrict__ dinv,
                       int* cursor, int* __restrict__ srcs, float* __restrict__ coefs,
                       int E) {
    int e = blockIdx.x * blockDim.x + threadIdx.x;
    if (e >= E) return;
    int s = src[e], d = dst[e];
    int pos = atomicAdd(&cursor[d], 1);
    srcs[pos]  = s;
    coefs[pos] = dinv[s] * w[e] * dinv[d];
}

// ---------------------------------------------------------------------------
// tf32 mma.sync GEMM: C[M,128] = A[M,K] @ B[K,128]
// CTA tile 128x128, BK=16, 8 warps, warp tile 32x64, m16n8k8, fp32 acc.
// ---------------------------------------------------------------------------
#define APITCH 20
#define BPITCH 136

__device__ __forceinline__ uint32_t f2tf32(float x) {
    uint32_t r;
    asm("cvt.rna.tf32.f32 %0, %1;" : "=r"(r) : "f"(x));
    return r;
}

__device__ __forceinline__ void mma_tf32(float* c, const uint32_t* a,
                                         uint32_t b0, uint32_t b1) {
    asm volatile(
        "mma.sync.aligned.m16n8k8.row.col.f32.tf32.tf32.f32 "
        "{%0,%1,%2,%3}, {%4,%5,%6,%7}, {%8,%9}, {%0,%1,%2,%3};"
        : "+f"(c[0]), "+f"(c[1]), "+f"(c[2]), "+f"(c[3])
        : "r"(a[0]), "r"(a[1]), "r"(a[2]), "r"(a[3]), "r"(b0), "r"(b1));
}

__global__ __launch_bounds__(256, 2)
void k_gemm_mma(const float* __restrict__ A, const float* __restrict__ B,
                float* __restrict__ C, int M, int K) {
    __shared__ __align__(16) float As[2][128 * APITCH];
    __shared__ __align__(16) float Bs[2][16 * BPITCH];

    const int tid  = threadIdx.x;
    const int lane = tid & 31;
    const int wid  = tid >> 5;
    const int warp_m = wid & 3;
    const int warp_n = wid >> 2;
    const int gp = lane >> 2;
    const int tg = lane & 3;
    const int m0 = blockIdx.x * 128;

    float acc[2][8][4];
#pragma unroll
    for (int i = 0; i < 2; i++)
#pragma unroll
        for (int j = 0; j < 8; j++)
#pragma unroll
            for (int q = 0; q < 4; q++) acc[i][j][q] = 0.0f;

    float4 pa[2], pb[2];

    auto load_regs = [&](int k0) {
#pragma unroll
        for (int u = 0; u < 2; u++) {
            int idx = tid + u * 256;
            int ar  = idx >> 2;
            int aq  = idx & 3;
            pa[u] = (m0 + ar < M)
                  ? *(const float4*)(A + (size_t)(m0 + ar) * K + k0 + aq * 4)
                  : make_float4(0.f, 0.f, 0.f, 0.f);
            int kr = idx >> 5;
            int bq = idx & 31;
            pb[u] = *(const float4*)(B + (size_t)(k0 + kr) * 128 + bq * 4);
        }
    };

    auto store_smem = [&](int buf) {
#pragma unroll
        for (int u = 0; u < 2; u++) {
            int idx = tid + u * 256;
            int ar  = idx >> 2;
            int aq  = idx & 3;
            uint32_t* d = (uint32_t*)&As[buf][ar * APITCH + aq * 4];
            d[0] = f2tf32(pa[u].x); d[1] = f2tf32(pa[u].y);
            d[2] = f2tf32(pa[u].z); d[3] = f2tf32(pa[u].w);
            int kr = idx >> 5;
            int bq = idx & 31;
            uint32_t* e = (uint32_t*)&Bs[buf][kr * BPITCH + bq * 4];
            e[0] = f2tf32(pb[u].x); e[1] = f2tf32(pb[u].y);
            e[2] = f2tf32(pb[u].z); e[3] = f2tf32(pb[u].w);
        }
    };

    const int niter = K / 16;
    load_regs(0);
    store_smem(0);

    for (int it = 0; it < niter; it++) {
        if (it + 1 < niter) load_regs((it + 1) * 16);
        __syncthreads();
        const int buf = it & 1;
        const uint32_t* as = (const uint32_t*)&As[buf][0];
        const uint32_t* bs = (const uint32_t*)&Bs[buf][0];

#pragma unroll
        for (int kk = 0; kk < 16; kk += 8) {
            uint32_t af[2][4];
#pragma unroll
            for (int i = 0; i < 2; i++) {
                int mr = warp_m * 32 + i * 16 + gp;
                af[i][0] = as[(mr    ) * APITCH + kk + tg    ];
                af[i][1] = as[(mr + 8) * APITCH + kk + tg    ];
                af[i][2] = as[(mr    ) * APITCH + kk + tg + 4];
                af[i][3] = as[(mr + 8) * APITCH + kk + tg + 4];
            }
#pragma unroll
            for (int j = 0; j < 8; j++) {
                int nb = warp_n * 64 + j * 8 + gp;
                uint32_t b0 = bs[(kk + tg    ) * BPITCH + nb];
                uint32_t b1 = bs[(kk + tg + 4) * BPITCH + nb];
#pragma unroll
                for (int i = 0; i < 2; i++)
                    mma_tf32(acc[i][j], af[i], b0, b1);
            }
        }
        if (it + 1 < niter) store_smem((it + 1) & 1);
    }

#pragma unroll
    for (int i = 0; i < 2; i++) {
        int r0 = m0 + warp_m * 32 + i * 16 + gp;
        int r1 = r0 + 8;
#pragma unroll
        for (int j = 0; j < 8; j++) {
            int col = warp_n * 64 + j * 8 + tg * 2;
            if (r0 < M)
                *(float2*)(C + (size_t)r0 * 128 + col) = make_float2(acc[i][j][0], acc[i][j][1]);
            if (r1 < M)
                *(float2*)(C + (size_t)r1 * 128 + col) = make_float2(acc[i][j][2], acc[i][j][3]);
        }
    }
}

// ---------------------------------------------------------------------------
// CSR aggregation + bias + erf-GELU, one warp per destination node.
// out[d,:] = gelu( h[d,:]*dinv[d]^2 + sum_e h[src_e,:]*coef_e + bias )
// ---------------------------------------------------------------------------
__device__ __forceinline__ float gelu_erf(float x) {
    return 0.5f * x * (1.0f + erff(x * 0.70710678118654752440f));
}

__global__ __launch_bounds__(256, 8)
void k_aggregate(const int* __restrict__ rowptr, const int* __restrict__ srcs,
                 const float* __restrict__ coefs, const float* __restrict__ h,
                 const float* __restrict__ dinv, const float* __restrict__ bias,
                 float* __restrict__ out, int n) {
    int node = (blockIdx.x * blockDim.x + threadIdx.x) >> 5;
    int lane = threadIdx.x & 31;
    if (node >= n) return;

    int beg = __ldg(&rowptr[node]);
    int end = __ldg(&rowptr[node + 1]);

    float d = __ldg(&dinv[node]);
    float c = d * d;
    float4 acc = ((const float4*)(h + (size_t)node * 128))[lane];
    acc.x *= c; acc.y *= c; acc.z *= c; acc.w *= c;

    for (int base = beg; base < end; base += 32) {
        int m = end - base;
        int   s_l = (lane < m) ? __ldg(&srcs[base + lane])  : 0;
        float w_l = (lane < m) ? __ldg(&coefs[base + lane]) : 0.0f;
        int cnt = m < 32 ? m : 32;
        for (int j = 0; j < cnt; j++) {
            int   s = __shfl_sync(0xffffffffu, s_l, j);
            float w = __shfl_sync(0xffffffffu, w_l, j);
            float4 v = ((const float4*)(h + (size_t)s * 128))[lane];
            acc.x = fmaf(v.x, w, acc.x);
            acc.y = fmaf(v.y, w, acc.y);
            acc.z = fmaf(v.z, w, acc.z);
            acc.w = fmaf(v.w, w, acc.w);
        }
    }

    float4 bb = ((const float4*)bias)[lane];
    acc.x = gelu_erf(acc.x + bb.x);
    acc.y = gelu_erf(acc.y + bb.y);
    acc.z = gelu_erf(acc.z + bb.z);
    acc.w = gelu_erf(acc.w + bb.w);
    ((float4*)(out + (size_t)node * 128))[lane] = acc;
}

// ---------------------------------------------------------------------------
// Launch
// ---------------------------------------------------------------------------
extern "C" void kernel_launch(void* const* d_in, const int* in_sizes, int n_in,
                              void* d_out, int out_size) {
    const float* x  = (const float*)d_in[0];
    const int*   ei = (const int*)  d_in[1];
    const float* ew = (const float*)d_in[2];
    const float* W1 = (const float*)d_in[3];
    const float* b1 = (const float*)d_in[4];
    const float* W2 = (const float*)d_in[5];
    const float* b2 = (const float*)d_in[6];
    float* out = (float*)d_out;

    const int n  = out_size / FDIM;       // 100000
    const int K1 = in_sizes[0] / n;       // 256
    const int E  = in_sizes[2];           // 1600000
    const int* src = ei;
    const int* dst = ei + E;

    float *deg, *dinv, *coefs, *h, *a;
    int *cnt, *rowptr, *cursor, *srcs;
    cudaGetSymbolAddress((void**)&deg,    g_deg);
    cudaGetSymbolAddress((void**)&dinv,   g_dinv);
    cudaGetSymbolAddress((void**)&cnt,    g_cnt);
    cudaGetSymbolAddress((void**)&rowptr, g_rowptr);
    cudaGetSymbolAddress((void**)&cursor, g_cursor);
    cudaGetSymbolAddress((void**)&srcs,   g_srcs);
    cudaGetSymbolAddress((void**)&coefs,  g_coefs);
    cudaGetSymbolAddress((void**)&h,      g_h);
    cudaGetSymbolAddress((void**)&a,      g_a);

    const int TB = 256;
    dim3 gn((n + TB - 1) / TB);
    dim3 ge((E + TB - 1) / TB);
    dim3 gagg(((size_t)n * 32 + TB - 1) / TB);
    dim3 ggemm((n + 127) / 128);

    // --- CSR-by-dst build + normalization (shared by both layers) ---
    k_init   <<<gn, TB>>>(deg, cnt, n);
    k_deg_cnt<<<ge, TB>>>(dst, ew, deg, cnt, E);
    k_dinv   <<<gn, TB>>>(deg, dinv, n);
    k_scan   <<<1, 1024>>>(cnt, rowptr, n, E);
    k_copy   <<<gn, TB>>>(rowptr, cursor, n);
    k_fill   <<<ge, TB>>>(src, dst, ew, dinv, cursor, srcs, coefs, E);

    // --- layer 1: h = x@W1 ; a = gelu(agg(h) + b1) ---
    k_gemm_mma <<<ggemm, 256>>>(x, W1, h, n, K1);
    k_aggregate<<<gagg, TB>>>(rowptr, srcs, coefs, h, dinv, b1, a, n);

    // --- layer 2: h = a@W2 ; out = gelu(agg(h) + b2) ---
    k_gemm_mma <<<ggemm, 256>>>(a, W2, h, n, FDIM);
    k_aggregate<<<gagg, TB>>>(rowptr, srcs, coefs, h, dinv, b2, out, n);
}

// round 5
// speedup vs baseline: 2.7248x; 1.2259x over previous
#include <cuda_runtime.h>
#include <math.h>
#include <stdint.h>

// ---------------------------------------------------------------------------
// Problem constants: N=100000 nodes, E=1600000 edges, dims 256 -> 128 -> 128.
// ---------------------------------------------------------------------------
#define NMAX 100000
#define EMAX 1600000
#define FDIM 128
#define SCAN_TB 1024
#define NSCAN_BLOCKS ((NMAX + SCAN_TB - 1) / SCAN_TB)   // 98

// Scratch (static device globals; no runtime allocation).
__device__ float g_deg   [NMAX];
__device__ float g_dinv  [NMAX];
__device__ int   g_cnt   [NMAX];
__device__ int   g_rowptr[NMAX + 1];
__device__ int   g_cursor[NMAX];
__device__ int   g_bsum  [NSCAN_BLOCKS];
__device__ int   g_srcs  [EMAX];     // CSR-by-dst: source node per slot
__device__ float g_coefs [EMAX];     // CSR-by-dst: edge coefficient per slot
__device__ float g_h     [(size_t)NMAX * FDIM];  // GEMM output
__device__ float g_a     [(size_t)NMAX * FDIM];  // layer-1 activation

// ---------------------------------------------------------------------------
// Degree / counts
// ---------------------------------------------------------------------------
__global__ void k_init(float* deg, int* cnt, int n) {
    int i = blockIdx.x * blockDim.x + threadIdx.x;
    if (i < n) { deg[i] = 1.0f; cnt[i] = 0; }
}

__global__ void k_deg_cnt(const int* __restrict__ dst, const float* __restrict__ w,
                          float* deg, int* cnt, int E) {
    int e = blockIdx.x * blockDim.x + threadIdx.x;
    if (e < E) {
        int d = dst[e];
        atomicAdd(&deg[d], w[e]);
        atomicAdd(&cnt[d], 1);
    }
}

__global__ void k_dinv(const float* __restrict__ deg, float* dinv, int n) {
    int i = blockIdx.x * blockDim.x + threadIdx.x;
    if (i < n) dinv[i] = rsqrtf(deg[i]);
}

// ---------------------------------------------------------------------------
// Device-wide exclusive scan of cnt -> rowptr (3 kernels, fully parallel).
// ---------------------------------------------------------------------------
__global__ __launch_bounds__(SCAN_TB)
void k_reduce(const int* __restrict__ cnt, int* __restrict__ bsum, int n) {
    __shared__ int wsum[32];
    int i = blockIdx.x * SCAN_TB + threadIdx.x;
    int v = (i < n) ? cnt[i] : 0;
#pragma unroll
    for (int d = 16; d > 0; d >>= 1) v += __shfl_down_sync(0xffffffffu, v, d);
    int lane = threadIdx.x & 31, wid = threadIdx.x >> 5;
    if (lane == 0) wsum[wid] = v;
    __syncthreads();
    if (wid == 0) {
        int s = wsum[lane];
#pragma unroll
        for (int d = 16; d > 0; d >>= 1) s += __shfl_down_sync(0xffffffffu, s, d);
        if (lane == 0) bsum[blockIdx.x] = s;
    }
}

// Single small block: exclusive scan of nblk (<=1024) block sums, in place.
__global__ __launch_bounds__(SCAN_TB)
void k_scan_sums(int* __restrict__ bsum, int nblk, int* __restrict__ rowptr,
                 int n, int E) {
    __shared__ int wsum[32];
    const int tid = threadIdx.x, lane = tid & 31, wid = tid >> 5;
    int v = (tid < nblk) ? bsum[tid] : 0;
    int x = v;
#pragma unroll
    for (int d = 1; d < 32; d <<= 1) {
        int y = __shfl_up_sync(0xffffffffu, x, d);
        if (lane >= d) x += y;
    }
    if (lane == 31) wsum[wid] = x;
    __syncthreads();
    if (wid == 0) {
        int s = wsum[lane];
#pragma unroll
        for (int d = 1; d < 32; d <<= 1) {
            int y = __shfl_up_sync(0xffffffffu, s, d);
            if (lane >= d) s += y;
        }
        wsum[lane] = s;
    }
    __syncthreads();
    int woff = wid ? wsum[wid - 1] : 0;
    if (tid < nblk) bsum[tid] = woff + x - v;   // exclusive
    if (tid == 0) rowptr[n] = E;
}

// Final pass: per-block exclusive scan + block offset; writes rowptr AND cursor.
__global__ __launch_bounds__(SCAN_TB)
void k_scan_final(const int* __restrict__ cnt, const int* __restrict__ bsum,
                  int* __restrict__ rowptr, int* __restrict__ cursor, int n) {
    __shared__ int wsum[32];
    const int tid = threadIdx.x, lane = tid & 31, wid = tid >> 5;
    int i = blockIdx.x * SCAN_TB + tid;
    int v = (i < n) ? cnt[i] : 0;
    int x = v;
#pragma unroll
    for (int d = 1; d < 32; d <<= 1) {
        int y = __shfl_up_sync(0xffffffffu, x, d);
        if (lane >= d) x += y;
    }
    if (lane == 31) wsum[wid] = x;
    __syncthreads();
    if (wid == 0) {
        int s = wsum[lane];
#pragma unroll
        for (int d = 1; d < 32; d <<= 1) {
            int y = __shfl_up_sync(0xffffffffu, s, d);
            if (lane >= d) s += y;
        }
        wsum[lane] = s;
    }
    __syncthreads();
    int woff = wid ? wsum[wid - 1] : 0;
    if (i < n) {
        int r = bsum[blockIdx.x] + woff + x - v;
        rowptr[i] = r;
        cursor[i] = r;
    }
}

// Fill CSR slots; also computes the per-edge GCN coefficient.
__global__ void k_fill(const int* __restrict__ src, const int* __restrict__ dst,
                       const float* __restrict__ w, const float* __restrict__ dinv,
                       int* cursor, int* __restrict__ srcs, float* __restrict__ coefs,
                       int E) {
    int e = blockIdx.x * blockDim.x + threadIdx.x;
    if (e >= E) return;
    int s = src[e], d = dst[e];
    int pos = atomicAdd(&cursor[d], 1);
    srcs[pos]  = s;
    coefs[pos] = dinv[s] * w[e] * dinv[d];
}

// ---------------------------------------------------------------------------
// tf32 mma.sync GEMM: C[M,128] = A[M,K] @ B[K,128]
// CTA tile 128x128, BK=16, 8 warps, warp tile 32x64, m16n8k8, fp32 acc.
// ---------------------------------------------------------------------------
#define APITCH 20
#define BPITCH 136

__device__ __forceinline__ uint32_t f2tf32(float x) {
    uint32_t r;
    asm("cvt.rna.tf32.f32 %0, %1;" : "=r"(r) : "f"(x));
    return r;
}

__device__ __forceinline__ void mma_tf32(float* c, const uint32_t* a,
                                         uint32_t b0, uint32_t b1) {
    asm volatile(
        "mma.sync.aligned.m16n8k8.row.col.f32.tf32.tf32.f32 "
        "{%0,%1,%2,%3}, {%4,%5,%6,%7}, {%8,%9}, {%0,%1,%2,%3};"
        : "+f"(c[0]), "+f"(c[1]), "+f"(c[2]), "+f"(c[3])
        : "r"(a[0]), "r"(a[1]), "r"(a[2]), "r"(a[3]), "r"(b0), "r"(b1));
}

__global__ __launch_bounds__(256, 2)
void k_gemm_mma(const float* __restrict__ A, const float* __restrict__ B,
                float* __restrict__ C, int M, int K) {
    __shared__ __align__(16) float As[2][128 * APITCH];
    __shared__ __align__(16) float Bs[2][16 * BPITCH];

    const int tid  = threadIdx.x;
    const int lane = tid & 31;
    const int wid  = tid >> 5;
    const int warp_m = wid & 3;
    const int warp_n = wid >> 2;
    const int gp = lane >> 2;
    const int tg = lane & 3;
    const int m0 = blockIdx.x * 128;

    float acc[2][8][4];
#pragma unroll
    for (int i = 0; i < 2; i++)
#pragma unroll
        for (int j = 0; j < 8; j++)
#pragma unroll
            for (int q = 0; q < 4; q++) acc[i][j][q] = 0.0f;

    float4 pa[2], pb[2];

    auto load_regs = [&](int k0) {
#pragma unroll
        for (int u = 0; u < 2; u++) {
            int idx = tid + u * 256;
            int ar  = idx >> 2;
            int aq  = idx & 3;
            pa[u] = (m0 + ar < M)
                  ? *(const float4*)(A + (size_t)(m0 + ar) * K + k0 + aq * 4)
                  : make_float4(0.f, 0.f, 0.f, 0.f);
            int kr = idx >> 5;
            int bq = idx & 31;
            pb[u] = *(const float4*)(B + (size_t)(k0 + kr) * 128 + bq * 4);
        }
    };

    auto store_smem = [&](int buf) {
#pragma unroll
        for (int u = 0; u < 2; u++) {
            int idx = tid + u * 256;
            int ar  = idx >> 2;
            int aq  = idx & 3;
            uint32_t* d = (uint32_t*)&As[buf][ar * APITCH + aq * 4];
            d[0] = f2tf32(pa[u].x); d[1] = f2tf32(pa[u].y);
            d[2] = f2tf32(pa[u].z); d[3] = f2tf32(pa[u].w);
            int kr = idx >> 5;
            int bq = idx & 31;
            uint32_t* e = (uint32_t*)&Bs[buf][kr * BPITCH + bq * 4];
            e[0] = f2tf32(pb[u].x); e[1] = f2tf32(pb[u].y);
            e[2] = f2tf32(pb[u].z); e[3] = f2tf32(pb[u].w);
        }
    };

    const int niter = K / 16;
    load_regs(0);
    store_smem(0);

    for (int it = 0; it < niter; it++) {
        if (it + 1 < niter) load_regs((it + 1) * 16);
        __syncthreads();
        const int buf = it & 1;
        const uint32_t* as = (const uint32_t*)&As[buf][0];
        const uint32_t* bs = (const uint32_t*)&Bs[buf][0];

#pragma unroll
        for (int kk = 0; kk < 16; kk += 8) {
            uint32_t af[2][4];
#pragma unroll
            for (int i = 0; i < 2; i++) {
                int mr = warp_m * 32 + i * 16 + gp;
                af[i][0] = as[(mr    ) * APITCH + kk + tg    ];
                af[i][1] = as[(mr + 8) * APITCH + kk + tg    ];
                af[i][2] = as[(mr    ) * APITCH + kk + tg + 4];
                af[i][3] = as[(mr + 8) * APITCH + kk + tg + 4];
            }
#pragma unroll
            for (int j = 0; j < 8; j++) {
                int nb = warp_n * 64 + j * 8 + gp;
                uint32_t b0 = bs[(kk + tg    ) * BPITCH + nb];
                uint32_t b1 = bs[(kk + tg + 4) * BPITCH + nb];
#pragma unroll
                for (int i = 0; i < 2; i++)
                    mma_tf32(acc[i][j], af[i], b0, b1);
            }
        }
        if (it + 1 < niter) store_smem((it + 1) & 1);
    }

#pragma unroll
    for (int i = 0; i < 2; i++) {
        int r0 = m0 + warp_m * 32 + i * 16 + gp;
        int r1 = r0 + 8;
#pragma unroll
        for (int j = 0; j < 8; j++) {
            int col = warp_n * 64 + j * 8 + tg * 2;
            if (r0 < M)
                *(float2*)(C + (size_t)r0 * 128 + col) = make_float2(acc[i][j][0], acc[i][j][1]);
            if (r1 < M)
                *(float2*)(C + (size_t)r1 * 128 + col) = make_float2(acc[i][j][2], acc[i][j][3]);
        }
    }
}

// ---------------------------------------------------------------------------
// CSR aggregation + bias + erf-GELU, one warp per destination node.
// out[d,:] = gelu( h[d,:]*dinv[d]^2 + sum_e h[src_e,:]*coef_e + bias )
// ---------------------------------------------------------------------------
__device__ __forceinline__ float gelu_erf(float x) {
    return 0.5f * x * (1.0f + erff(x * 0.70710678118654752440f));
}

__global__ __launch_bounds__(256, 8)
void k_aggregate(const int* __restrict__ rowptr, const int* __restrict__ srcs,
                 const float* __restrict__ coefs, const float* __restrict__ h,
                 const float* __restrict__ dinv, const float* __restrict__ bias,
                 float* __restrict__ out, int n) {
    int node = (blockIdx.x * blockDim.x + threadIdx.x) >> 5;
    int lane = threadIdx.x & 31;
    if (node >= n) return;

    int beg = __ldg(&rowptr[node]);
    int end = __ldg(&rowptr[node + 1]);

    float d = __ldg(&dinv[node]);
    float c = d * d;
    float4 acc = ((const float4*)(h + (size_t)node * 128))[lane];
    acc.x *= c; acc.y *= c; acc.z *= c; acc.w *= c;

    for (int base = beg; base < end; base += 32) {
        int m = end - base;
        int   s_l = (lane < m) ? __ldg(&srcs[base + lane])  : 0;
        float w_l = (lane < m) ? __ldg(&coefs[base + lane]) : 0.0f;
        int cnt = m < 32 ? m : 32;
        for (int j = 0; j < cnt; j++) {
            int   s = __shfl_sync(0xffffffffu, s_l, j);
            float w = __shfl_sync(0xffffffffu, w_l, j);
            float4 v = ((const float4*)(h + (size_t)s * 128))[lane];
            acc.x = fmaf(v.x, w, acc.x);
            acc.y = fmaf(v.y, w, acc.y);
            acc.z = fmaf(v.z, w, acc.z);
            acc.w = fmaf(v.w, w, acc.w);
        }
    }

    float4 bb = ((const float4*)bias)[lane];
    acc.x = gelu_erf(acc.x + bb.x);
    acc.y = gelu_erf(acc.y + bb.y);
    acc.z = gelu_erf(acc.z + bb.z);
    acc.w = gelu_erf(acc.w + bb.w);
    ((float4*)(out + (size_t)node * 128))[lane] = acc;
}

// ---------------------------------------------------------------------------
// Launch
// ---------------------------------------------------------------------------
extern "C" void kernel_launch(void* const* d_in, const int* in_sizes, int n_in,
                              void* d_out, int out_size) {
    const float* x  = (const float*)d_in[0];
    const int*   ei = (const int*)  d_in[1];
    const float* ew = (const float*)d_in[2];
    const float* W1 = (const float*)d_in[3];
    const float* b1 = (const float*)d_in[4];
    const float* W2 = (const float*)d_in[5];
    const float* b2 = (const float*)d_in[6];
    float* out = (float*)d_out;

    const int n  = out_size / FDIM;       // 100000
    const int K1 = in_sizes[0] / n;       // 256
    const int E  = in_sizes[2];           // 1600000
    const int* src = ei;
    const int* dst = ei + E;

    float *deg, *dinv, *coefs, *h, *a;
    int *cnt, *rowptr, *cursor, *srcs, *bsum;
    cudaGetSymbolAddress((void**)&deg,    g_deg);
    cudaGetSymbolAddress((void**)&dinv,   g_dinv);
    cudaGetSymbolAddress((void**)&cnt,    g_cnt);
    cudaGetSymbolAddress((void**)&rowptr, g_rowptr);
    cudaGetSymbolAddress((void**)&cursor, g_cursor);
    cudaGetSymbolAddress((void**)&srcs,   g_srcs);
    cudaGetSymbolAddress((void**)&coefs,  g_coefs);
    cudaGetSymbolAddress((void**)&h,      g_h);
    cudaGetSymbolAddress((void**)&a,      g_a);
    cudaGetSymbolAddress((void**)&bsum,   g_bsum);

    const int TB = 256;
    const int nblk = (n + SCAN_TB - 1) / SCAN_TB;
    dim3 gn((n + TB - 1) / TB);
    dim3 ge((E + TB - 1) / TB);
    dim3 gagg(((size_t)n * 32 + TB - 1) / TB);
    dim3 ggemm((n + 127) / 128);

    // --- CSR-by-dst build + normalization (shared by both layers) ---
    k_init      <<<gn, TB>>>(deg, cnt, n);
    k_deg_cnt   <<<ge, TB>>>(dst, ew, deg, cnt, E);
    k_dinv      <<<gn, TB>>>(deg, dinv, n);
    k_reduce    <<<nblk, SCAN_TB>>>(cnt, bsum, n);
    k_scan_sums <<<1, SCAN_TB>>>(bsum, nblk, rowptr, n, E);
    k_scan_final<<<nblk, SCAN_TB>>>(cnt, bsum, rowptr, cursor, n);
    k_fill      <<<ge, TB>>>(src, dst, ew, dinv, cursor, srcs, coefs, E);

    // --- layer 1: h = x@W1 ; a = gelu(agg(h) + b1) ---
    k_gemm_mma <<<ggemm, 256>>>(x, W1, h, n, K1);
    k_aggregate<<<gagg, TB>>>(rowptr, srcs, coefs, h, dinv, b1, a, n);

    // --- layer 2: h = a@W2 ; out = gelu(agg(h) + b2) ---
    k_gemm_mma <<<ggemm, 256>>>(a, W2, h, n, FDIM);
    k_aggregate<<<gagg, TB>>>(rowptr, srcs, coefs, h, dinv, b2, out, n);
}

// round 6
// speedup vs baseline: 2.9551x; 1.0845x over previous
#include <cuda_runtime.h>
#include <cuda_fp16.h>
#include <math.h>
#include <stdint.h>

// ---------------------------------------------------------------------------
// Problem constants: N=100000 nodes, E=1600000 edges, dims 256 -> 128 -> 128.
// ---------------------------------------------------------------------------
#define NMAX 100000
#define EMAX 1600000
#define FDIM 128
#define SCAN_TB 1024
#define NSCAN_BLOCKS ((NMAX + SCAN_TB - 1) / SCAN_TB)   // 98

// Scratch (static device globals; no runtime allocation).
__device__ float  g_deg   [NMAX];
__device__ float  g_dinv  [NMAX];
__device__ int    g_cnt   [NMAX];
__device__ int    g_rowptr[NMAX + 1];
__device__ int    g_cursor[NMAX];
__device__ int    g_bsum  [NSCAN_BLOCKS];
__device__ int    g_srcs  [EMAX];     // CSR-by-dst: source node per slot
__device__ float  g_coefs [EMAX];     // CSR-by-dst: edge coefficient per slot
__device__ __half g_h     [(size_t)NMAX * FDIM];  // GEMM output (fp16 storage)
__device__ float  g_a     [(size_t)NMAX * FDIM];  // layer-1 activation (fp32)

// ---------------------------------------------------------------------------
// Degree / counts
// ---------------------------------------------------------------------------
__global__ void k_init(float* deg, int* cnt, int n) {
    int i = blockIdx.x * blockDim.x + threadIdx.x;
    if (i < n) { deg[i] = 1.0f; cnt[i] = 0; }
}

__global__ void k_deg_cnt(const int* __restrict__ dst, const float* __restrict__ w,
                          float* deg, int* cnt, int E) {
    int e = blockIdx.x * blockDim.x + threadIdx.x;
    if (e < E) {
        int d = dst[e];
        atomicAdd(&deg[d], w[e]);
        atomicAdd(&cnt[d], 1);
    }
}

__global__ void k_dinv(const float* __restrict__ deg, float* dinv, int n) {
    int i = blockIdx.x * blockDim.x + threadIdx.x;
    if (i < n) dinv[i] = rsqrtf(deg[i]);
}

// ---------------------------------------------------------------------------
// Device-wide exclusive scan of cnt -> rowptr (3 kernels, fully parallel).
// ---------------------------------------------------------------------------
__global__ __launch_bounds__(SCAN_TB)
void k_reduce(const int* __restrict__ cnt, int* __restrict__ bsum, int n) {
    __shared__ int wsum[32];
    int i = blockIdx.x * SCAN_TB + threadIdx.x;
    int v = (i < n) ? cnt[i] : 0;
#pragma unroll
    for (int d = 16; d > 0; d >>= 1) v += __shfl_down_sync(0xffffffffu, v, d);
    int lane = threadIdx.x & 31, wid = threadIdx.x >> 5;
    if (lane == 0) wsum[wid] = v;
    __syncthreads();
    if (wid == 0) {
        int s = wsum[lane];
#pragma unroll
        for (int d = 16; d > 0; d >>= 1) s += __shfl_down_sync(0xffffffffu, s, d);
        if (lane == 0) bsum[blockIdx.x] = s;
    }
}

__global__ __launch_bounds__(SCAN_TB)
void k_scan_sums(int* __restrict__ bsum, int nblk, int* __restrict__ rowptr,
                 int n, int E) {
    __shared__ int wsum[32];
    const int tid = threadIdx.x, lane = tid & 31, wid = tid >> 5;
    int v = (tid < nblk) ? bsum[tid] : 0;
    int x = v;
#pragma unroll
    for (int d = 1; d < 32; d <<= 1) {
        int y = __shfl_up_sync(0xffffffffu, x, d);
        if (lane >= d) x += y;
    }
    if (lane == 31) wsum[wid] = x;
    __syncthreads();
    if (wid == 0) {
        int s = wsum[lane];
#pragma unroll
        for (int d = 1; d < 32; d <<= 1) {
            int y = __shfl_up_sync(0xffffffffu, s, d);
            if (lane >= d) s += y;
        }
        wsum[lane] = s;
    }
    __syncthreads();
    int woff = wid ? wsum[wid - 1] : 0;
    if (tid < nblk) bsum[tid] = woff + x - v;   // exclusive
    if (tid == 0) rowptr[n] = E;
}

__global__ __launch_bounds__(SCAN_TB)
void k_scan_final(const int* __restrict__ cnt, const int* __restrict__ bsum,
                  int* __restrict__ rowptr, int* __restrict__ cursor, int n) {
    __shared__ int wsum[32];
    const int tid = threadIdx.x, lane = tid & 31, wid = tid >> 5;
    int i = blockIdx.x * SCAN_TB + tid;
    int v = (i < n) ? cnt[i] : 0;
    int x = v;
#pragma unroll
    for (int d = 1; d < 32; d <<= 1) {
        int y = __shfl_up_sync(0xffffffffu, x, d);
        if (lane >= d) x += y;
    }
    if (lane == 31) wsum[wid] = x;
    __syncthreads();
    if (wid == 0) {
        int s = wsum[lane];
#pragma unroll
        for (int d = 1; d < 32; d <<= 1) {
            int y = __shfl_up_sync(0xffffffffu, s, d);
            if (lane >= d) s += y;
        }
        wsum[lane] = s;
    }
    __syncthreads();
    int woff = wid ? wsum[wid - 1] : 0;
    if (i < n) {
        int r = bsum[blockIdx.x] + woff + x - v;
        rowptr[i] = r;
        cursor[i] = r;
    }
}

// Fill CSR slots; also computes the per-edge GCN coefficient.
__global__ void k_fill(const int* __restrict__ src, const int* __restrict__ dst,
                       const float* __restrict__ w, const float* __restrict__ dinv,
                       int* cursor, int* __restrict__ srcs, float* __restrict__ coefs,
                       int E) {
    int e = blockIdx.x * blockDim.x + threadIdx.x;
    if (e >= E) return;
    int s = src[e], d = dst[e];
    int pos = atomicAdd(&cursor[d], 1);
    srcs[pos]  = s;
    coefs[pos] = dinv[s] * w[e] * dinv[d];
}

// ---------------------------------------------------------------------------
// tf32 mma.sync GEMM: C[M,128] = A[M,K] @ B[K,128], epilogue stores fp16.
// CTA tile 128x128, BK=16, 8 warps, warp tile 32x64, m16n8k8, fp32 acc.
// ---------------------------------------------------------------------------
#define APITCH 20
#define BPITCH 136

__device__ __forceinline__ uint32_t f2tf32(float x) {
    uint32_t r;
    asm("cvt.rna.tf32.f32 %0, %1;" : "=r"(r) : "f"(x));
    return r;
}

__device__ __forceinline__ void mma_tf32(float* c, const uint32_t* a,
                                         uint32_t b0, uint32_t b1) {
    asm volatile(
        "mma.sync.aligned.m16n8k8.row.col.f32.tf32.tf32.f32 "
        "{%0,%1,%2,%3}, {%4,%5,%6,%7}, {%8,%9}, {%0,%1,%2,%3};"
        : "+f"(c[0]), "+f"(c[1]), "+f"(c[2]), "+f"(c[3])
        : "r"(a[0]), "r"(a[1]), "r"(a[2]), "r"(a[3]), "r"(b0), "r"(b1));
}

__global__ __launch_bounds__(256, 2)
void k_gemm_mma(const float* __restrict__ A, const float* __restrict__ B,
                __half* __restrict__ C, int M, int K) {
    __shared__ __align__(16) float As[2][128 * APITCH];
    __shared__ __align__(16) float Bs[2][16 * BPITCH];

    const int tid  = threadIdx.x;
    const int lane = tid & 31;
    const int wid  = tid >> 5;
    const int warp_m = wid & 3;
    const int warp_n = wid >> 2;
    const int gp = lane >> 2;
    const int tg = lane & 3;
    const int m0 = blockIdx.x * 128;

    float acc[2][8][4];
#pragma unroll
    for (int i = 0; i < 2; i++)
#pragma unroll
        for (int j = 0; j < 8; j++)
#pragma unroll
            for (int q = 0; q < 4; q++) acc[i][j][q] = 0.0f;

    float4 pa[2], pb[2];

    auto load_regs = [&](int k0) {
#pragma unroll
        for (int u = 0; u < 2; u++) {
            int idx = tid + u * 256;
            int ar  = idx >> 2;
            int aq  = idx & 3;
            pa[u] = (m0 + ar < M)
                  ? *(const float4*)(A + (size_t)(m0 + ar) * K + k0 + aq * 4)
                  : make_float4(0.f, 0.f, 0.f, 0.f);
            int kr = idx >> 5;
            int bq = idx & 31;
            pb[u] = *(const float4*)(B + (size_t)(k0 + kr) * 128 + bq * 4);
        }
    };

    auto store_smem = [&](int buf) {
#pragma unroll
        for (int u = 0; u < 2; u++) {
            int idx = tid + u * 256;
            int ar  = idx >> 2;
            int aq  = idx & 3;
            uint32_t* d = (uint32_t*)&As[buf][ar * APITCH + aq * 4];
            d[0] = f2tf32(pa[u].x); d[1] = f2tf32(pa[u].y);
            d[2] = f2tf32(pa[u].z); d[3] = f2tf32(pa[u].w);
            int kr = idx >> 5;
            int bq = idx & 31;
            uint32_t* e = (uint32_t*)&Bs[buf][kr * BPITCH + bq * 4];
            e[0] = f2tf32(pb[u].x); e[1] = f2tf32(pb[u].y);
            e[2] = f2tf32(pb[u].z); e[3] = f2tf32(pb[u].w);
        }
    };

    const int niter = K / 16;
    load_regs(0);
    store_smem(0);

    for (int it = 0; it < niter; it++) {
        if (it + 1 < niter) load_regs((it + 1) * 16);
        __syncthreads();
        const int buf = it & 1;
        const uint32_t* as = (const uint32_t*)&As[buf][0];
        const uint32_t* bs = (const uint32_t*)&Bs[buf][0];

#pragma unroll
        for (int kk = 0; kk < 16; kk += 8) {
            uint32_t af[2][4];
#pragma unroll
            for (int i = 0; i < 2; i++) {
                int mr = warp_m * 32 + i * 16 + gp;
                af[i][0] = as[(mr    ) * APITCH + kk + tg    ];
                af[i][1] = as[(mr + 8) * APITCH + kk + tg    ];
                af[i][2] = as[(mr    ) * APITCH + kk + tg + 4];
                af[i][3] = as[(mr + 8) * APITCH + kk + tg + 4];
            }
#pragma unroll
            for (int j = 0; j < 8; j++) {
                int nb = warp_n * 64 + j * 8 + gp;
                uint32_t b0 = bs[(kk + tg    ) * BPITCH + nb];
                uint32_t b1 = bs[(kk + tg + 4) * BPITCH + nb];
#pragma unroll
                for (int i = 0; i < 2; i++)
                    mma_tf32(acc[i][j], af[i], b0, b1);
            }
        }
        if (it + 1 < niter) store_smem((it + 1) & 1);
    }

#pragma unroll
    for (int i = 0; i < 2; i++) {
        int r0 = m0 + warp_m * 32 + i * 16 + gp;
        int r1 = r0 + 8;
#pragma unroll
        for (int j = 0; j < 8; j++) {
            int col = warp_n * 64 + j * 8 + tg * 2;
            if (r0 < M)
                *(__half2*)(C + (size_t)r0 * 128 + col) =
                    __floats2half2_rn(acc[i][j][0], acc[i][j][1]);
            if (r1 < M)
                *(__half2*)(C + (size_t)r1 * 128 + col) =
                    __floats2half2_rn(acc[i][j][2], acc[i][j][3]);
        }
    }
}

// ---------------------------------------------------------------------------
// CSR aggregation + bias + erf-GELU, one warp per destination node.
// h is fp16; accumulation in fp32. Each lane handles 4 columns (8B load/row).
// out[d,:] = gelu( h[d,:]*dinv[d]^2 + sum_e h[src_e,:]*coef_e + bias )
// ---------------------------------------------------------------------------
__device__ __forceinline__ float gelu_erf(float x) {
    return 0.5f * x * (1.0f + erff(x * 0.70710678118654752440f));
}

__device__ __forceinline__ float4 load_h4(const __half* __restrict__ h,
                                          size_t row, int lane) {
    float2 raw = ((const float2*)(h + row * 128))[lane];   // 8B = 4 halves
    __half2 p0 = *(__half2*)&raw.x;
    __half2 p1 = *(__half2*)&raw.y;
    float2 f0 = __half22float2(p0);
    float2 f1 = __half22float2(p1);
    return make_float4(f0.x, f0.y, f1.x, f1.y);
}

__global__ __launch_bounds__(256, 8)
void k_aggregate(const int* __restrict__ rowptr, const int* __restrict__ srcs,
                 const float* __restrict__ coefs, const __half* __restrict__ h,
                 const float* __restrict__ dinv, const float* __restrict__ bias,
                 float* __restrict__ out, int n) {
    int node = (blockIdx.x * blockDim.x + threadIdx.x) >> 5;
    int lane = threadIdx.x & 31;
    if (node >= n) return;

    int beg = __ldg(&rowptr[node]);
    int end = __ldg(&rowptr[node + 1]);

    float d = __ldg(&dinv[node]);
    float c = d * d;
    float4 acc = load_h4(h, (size_t)node, lane);
    acc.x *= c; acc.y *= c; acc.z *= c; acc.w *= c;

    for (int base = beg; base < end; base += 32) {
        int m = end - base;
        int   s_l = (lane < m) ? __ldg(&srcs[base + lane])  : 0;
        float w_l = (lane < m) ? __ldg(&coefs[base + lane]) : 0.0f;
        int cnt = m < 32 ? m : 32;
        for (int j = 0; j < cnt; j++) {
            int   s = __shfl_sync(0xffffffffu, s_l, j);
            float w = __shfl_sync(0xffffffffu, w_l, j);
            float4 v = load_h4(h, (size_t)s, lane);
            acc.x = fmaf(v.x, w, acc.x);
            acc.y = fmaf(v.y, w, acc.y);
            acc.z = fmaf(v.z, w, acc.z);
            acc.w = fmaf(v.w, w, acc.w);
        }
    }

    float4 bb = ((const float4*)bias)[lane];   // lane*16B -> 4 floats
    acc.x = gelu_erf(acc.x + bb.x);
    acc.y = gelu_erf(acc.y + bb.y);
    acc.z = gelu_erf(acc.z + bb.z);
    acc.w = gelu_erf(acc.w + bb.w);
    ((float4*)(out + (size_t)node * 128))[lane] = acc;
}

// ---------------------------------------------------------------------------
// Launch
// ---------------------------------------------------------------------------
extern "C" void kernel_launch(void* const* d_in, const int* in_sizes, int n_in,
                              void* d_out, int out_size) {
    const float* x  = (const float*)d_in[0];
    const int*   ei = (const int*)  d_in[1];
    const float* ew = (const float*)d_in[2];
    const float* W1 = (const float*)d_in[3];
    const float* b1 = (const float*)d_in[4];
    const float* W2 = (const float*)d_in[5];
    const float* b2 = (const float*)d_in[6];
    float* out = (float*)d_out;

    const int n  = out_size / FDIM;       // 100000
    const int K1 = in_sizes[0] / n;       // 256
    const int E  = in_sizes[2];           // 1600000
    const int* src = ei;
    const int* dst = ei + E;

    float *deg, *dinv, *coefs, *a;
    __half* h;
    int *cnt, *rowptr, *cursor, *srcs, *bsum;
    cudaGetSymbolAddress((void**)&deg,    g_deg);
    cudaGetSymbolAddress((void**)&dinv,   g_dinv);
    cudaGetSymbolAddress((void**)&cnt,    g_cnt);
    cudaGetSymbolAddress((void**)&rowptr, g_rowptr);
    cudaGetSymbolAddress((void**)&cursor, g_cursor);
    cudaGetSymbolAddress((void**)&srcs,   g_srcs);
    cudaGetSymbolAddress((void**)&coefs,  g_coefs);
    cudaGetSymbolAddress((void**)&h,      g_h);
    cudaGetSymbolAddress((void**)&a,      g_a);
    cudaGetSymbolAddress((void**)&bsum,   g_bsum);

    const int TB = 256;
    const int nblk = (n + SCAN_TB - 1) / SCAN_TB;
    dim3 gn((n + TB - 1) / TB);
    dim3 ge((E + TB - 1) / TB);
    dim3 gagg(((size_t)n * 32 + TB - 1) / TB);
    dim3 ggemm((n + 127) / 128);

    // --- CSR-by-dst build + normalization (shared by both layers) ---
    k_init      <<<gn, TB>>>(deg, cnt, n);
    k_deg_cnt   <<<ge, TB>>>(dst, ew, deg, cnt, E);
    k_dinv      <<<gn, TB>>>(deg, dinv, n);
    k_reduce    <<<nblk, SCAN_TB>>>(cnt, bsum, n);
    k_scan_sums <<<1, SCAN_TB>>>(bsum, nblk, rowptr, n, E);
    k_scan_final<<<nblk, SCAN_TB>>>(cnt, bsum, rowptr, cursor, n);
    k_fill      <<<ge, TB>>>(src, dst, ew, dinv, cursor, srcs, coefs, E);

    // --- layer 1: h = x@W1 (fp16) ; a = gelu(agg(h) + b1) ---
    k_gemm_mma <<<ggemm, 256>>>(x, W1, h, n, K1);
    k_aggregate<<<gagg, TB>>>(rowptr, srcs, coefs, h, dinv, b1, a, n);

    // --- layer 2: h = a@W2 (fp16) ; out = gelu(agg(h) + b2) ---
    k_gemm_mma <<<ggemm, 256>>>(a, W2, h, n, FDIM);
    k_aggregate<<<gagg, TB>>>(rowptr, srcs, coefs, h, dinv, b2, out, n);
}

// round 7
// speedup vs baseline: 3.0069x; 1.0176x over previous
#include <cuda_runtime.h>
#include <cuda_fp16.h>
#include <math.h>
#include <stdint.h>

// ---------------------------------------------------------------------------
// Problem constants: N=100000 nodes, E=1600000 edges, dims 256 -> 128 -> 128.
// ---------------------------------------------------------------------------
#define NMAX 100000
#define EMAX 1600000
#define FDIM 128
#define SCAN_TB 1024
#define NSCAN_BLOCKS ((NMAX + SCAN_TB - 1) / SCAN_TB)   // 98

// Scratch (static device globals; no runtime allocation).
__device__ float  g_deg   [NMAX];
__device__ float  g_dinv  [NMAX];
__device__ int    g_cnt   [NMAX];
__device__ int    g_rowptr[NMAX + 1];
__device__ int    g_cursor[NMAX];
__device__ int    g_bsum  [NSCAN_BLOCKS];
__device__ int    g_srcs  [EMAX];     // CSR-by-dst: source node per slot
__device__ float  g_coefs [EMAX];     // CSR-by-dst: edge coefficient per slot
__device__ __half g_h     [(size_t)NMAX * FDIM];  // GEMM output (fp16 storage)
__device__ float  g_a     [(size_t)NMAX * FDIM];  // layer-1 activation (fp32)

// ---------------------------------------------------------------------------
// Degree / counts
// ---------------------------------------------------------------------------
__global__ void k_init(float* deg, int* cnt, int n) {
    int i = blockIdx.x * blockDim.x + threadIdx.x;
    if (i < n) { deg[i] = 1.0f; cnt[i] = 0; }
}

__global__ void k_deg_cnt(const int* __restrict__ dst, const float* __restrict__ w,
                          float* deg, int* cnt, int E) {
    int e = blockIdx.x * blockDim.x + threadIdx.x;
    if (e < E) {
        int d = dst[e];
        atomicAdd(&deg[d], w[e]);
        atomicAdd(&cnt[d], 1);
    }
}

__global__ void k_dinv(const float* __restrict__ deg, float* dinv, int n) {
    int i = blockIdx.x * blockDim.x + threadIdx.x;
    if (i < n) dinv[i] = rsqrtf(deg[i]);
}

// ---------------------------------------------------------------------------
// Device-wide exclusive scan of cnt -> rowptr (3 kernels, fully parallel).
// ---------------------------------------------------------------------------
__global__ __launch_bounds__(SCAN_TB)
void k_reduce(const int* __restrict__ cnt, int* __restrict__ bsum, int n) {
    __shared__ int wsum[32];
    int i = blockIdx.x * SCAN_TB + threadIdx.x;
    int v = (i < n) ? cnt[i] : 0;
#pragma unroll
    for (int d = 16; d > 0; d >>= 1) v += __shfl_down_sync(0xffffffffu, v, d);
    int lane = threadIdx.x & 31, wid = threadIdx.x >> 5;
    if (lane == 0) wsum[wid] = v;
    __syncthreads();
    if (wid == 0) {
        int s = wsum[lane];
#pragma unroll
        for (int d = 16; d > 0; d >>= 1) s += __shfl_down_sync(0xffffffffu, s, d);
        if (lane == 0) bsum[blockIdx.x] = s;
    }
}

__global__ __launch_bounds__(SCAN_TB)
void k_scan_sums(int* __restrict__ bsum, int nblk, int* __restrict__ rowptr,
                 int n, int E) {
    __shared__ int wsum[32];
    const int tid = threadIdx.x, lane = tid & 31, wid = tid >> 5;
    int v = (tid < nblk) ? bsum[tid] : 0;
    int x = v;
#pragma unroll
    for (int d = 1; d < 32; d <<= 1) {
        int y = __shfl_up_sync(0xffffffffu, x, d);
        if (lane >= d) x += y;
    }
    if (lane == 31) wsum[wid] = x;
    __syncthreads();
    if (wid == 0) {
        int s = wsum[lane];
#pragma unroll
        for (int d = 1; d < 32; d <<= 1) {
            int y = __shfl_up_sync(0xffffffffu, s, d);
            if (lane >= d) s += y;
        }
        wsum[lane] = s;
    }
    __syncthreads();
    int woff = wid ? wsum[wid - 1] : 0;
    if (tid < nblk) bsum[tid] = woff + x - v;   // exclusive
    if (tid == 0) rowptr[n] = E;
}

__global__ __launch_bounds__(SCAN_TB)
void k_scan_final(const int* __restrict__ cnt, const int* __restrict__ bsum,
                  int* __restrict__ rowptr, int* __restrict__ cursor, int n) {
    __shared__ int wsum[32];
    const int tid = threadIdx.x, lane = tid & 31, wid = tid >> 5;
    int i = blockIdx.x * SCAN_TB + tid;
    int v = (i < n) ? cnt[i] : 0;
    int x = v;
#pragma unroll
    for (int d = 1; d < 32; d <<= 1) {
        int y = __shfl_up_sync(0xffffffffu, x, d);
        if (lane >= d) x += y;
    }
    if (lane == 31) wsum[wid] = x;
    __syncthreads();
    if (wid == 0) {
        int s = wsum[lane];
#pragma unroll
        for (int d = 1; d < 32; d <<= 1) {
            int y = __shfl_up_sync(0xffffffffu, s, d);
            if (lane >= d) s += y;
        }
        wsum[lane] = s;
    }
    __syncthreads();
    int woff = wid ? wsum[wid - 1] : 0;
    if (i < n) {
        int r = bsum[blockIdx.x] + woff + x - v;
        rowptr[i] = r;
        cursor[i] = r;
    }
}

// Fill CSR slots; also computes the per-edge GCN coefficient.
__global__ void k_fill(const int* __restrict__ src, const int* __restrict__ dst,
                       const float* __restrict__ w, const float* __restrict__ dinv,
                       int* cursor, int* __restrict__ srcs, float* __restrict__ coefs,
                       int E) {
    int e = blockIdx.x * blockDim.x + threadIdx.x;
    if (e >= E) return;
    int s = src[e], d = dst[e];
    int pos = atomicAdd(&cursor[d], 1);
    srcs[pos]  = s;
    coefs[pos] = dinv[s] * w[e] * dinv[d];
}

// ---------------------------------------------------------------------------
// tf32 mma.sync GEMM: C[M,128] = A[M,K] @ B[K,128], epilogue stores fp16.
// CTA tile 128x128, BK=16, 8 warps, warp tile 32x64, m16n8k8, fp32 acc.
// ---------------------------------------------------------------------------
#define APITCH 20
#define BPITCH 136

__device__ __forceinline__ uint32_t f2tf32(float x) {
    uint32_t r;
    asm("cvt.rna.tf32.f32 %0, %1;" : "=r"(r) : "f"(x));
    return r;
}

__device__ __forceinline__ void mma_tf32(float* c, const uint32_t* a,
                                         uint32_t b0, uint32_t b1) {
    asm volatile(
        "mma.sync.aligned.m16n8k8.row.col.f32.tf32.tf32.f32 "
        "{%0,%1,%2,%3}, {%4,%5,%6,%7}, {%8,%9}, {%0,%1,%2,%3};"
        : "+f"(c[0]), "+f"(c[1]), "+f"(c[2]), "+f"(c[3])
        : "r"(a[0]), "r"(a[1]), "r"(a[2]), "r"(a[3]), "r"(b0), "r"(b1));
}

__global__ __launch_bounds__(256, 2)
void k_gemm_mma(const float* __restrict__ A, const float* __restrict__ B,
                __half* __restrict__ C, int M, int K) {
    __shared__ __align__(16) float As[2][128 * APITCH];
    __shared__ __align__(16) float Bs[2][16 * BPITCH];

    const int tid  = threadIdx.x;
    const int lane = tid & 31;
    const int wid  = tid >> 5;
    const int warp_m = wid & 3;
    const int warp_n = wid >> 2;
    const int gp = lane >> 2;
    const int tg = lane & 3;
    const int m0 = blockIdx.x * 128;

    float acc[2][8][4];
#pragma unroll
    for (int i = 0; i < 2; i++)
#pragma unroll
        for (int j = 0; j < 8; j++)
#pragma unroll
            for (int q = 0; q < 4; q++) acc[i][j][q] = 0.0f;

    float4 pa[2], pb[2];

    auto load_regs = [&](int k0) {
#pragma unroll
        for (int u = 0; u < 2; u++) {
            int idx = tid + u * 256;
            int ar  = idx >> 2;
            int aq  = idx & 3;
            pa[u] = (m0 + ar < M)
                  ? *(const float4*)(A + (size_t)(m0 + ar) * K + k0 + aq * 4)
                  : make_float4(0.f, 0.f, 0.f, 0.f);
            int kr = idx >> 5;
            int bq = idx & 31;
            pb[u] = *(const float4*)(B + (size_t)(k0 + kr) * 128 + bq * 4);
        }
    };

    auto store_smem = [&](int buf) {
#pragma unroll
        for (int u = 0; u < 2; u++) {
            int idx = tid + u * 256;
            int ar  = idx >> 2;
            int aq  = idx & 3;
            uint32_t* d = (uint32_t*)&As[buf][ar * APITCH + aq * 4];
            d[0] = f2tf32(pa[u].x); d[1] = f2tf32(pa[u].y);
            d[2] = f2tf32(pa[u].z); d[3] = f2tf32(pa[u].w);
            int kr = idx >> 5;
            int bq = idx & 31;
            uint32_t* e = (uint32_t*)&Bs[buf][kr * BPITCH + bq * 4];
            e[0] = f2tf32(pb[u].x); e[1] = f2tf32(pb[u].y);
            e[2] = f2tf32(pb[u].z); e[3] = f2tf32(pb[u].w);
        }
    };

    const int niter = K / 16;
    load_regs(0);
    store_smem(0);

    for (int it = 0; it < niter; it++) {
        if (it + 1 < niter) load_regs((it + 1) * 16);
        __syncthreads();
        const int buf = it & 1;
        const uint32_t* as = (const uint32_t*)&As[buf][0];
        const uint32_t* bs = (const uint32_t*)&Bs[buf][0];

#pragma unroll
        for (int kk = 0; kk < 16; kk += 8) {
            uint32_t af[2][4];
#pragma unroll
            for (int i = 0; i < 2; i++) {
                int mr = warp_m * 32 + i * 16 + gp;
                af[i][0] = as[(mr    ) * APITCH + kk + tg    ];
                af[i][1] = as[(mr + 8) * APITCH + kk + tg    ];
                af[i][2] = as[(mr    ) * APITCH + kk + tg + 4];
                af[i][3] = as[(mr + 8) * APITCH + kk + tg + 4];
            }
#pragma unroll
            for (int j = 0; j < 8; j++) {
                int nb = warp_n * 64 + j * 8 + gp;
                uint32_t b0 = bs[(kk + tg    ) * BPITCH + nb];
                uint32_t b1 = bs[(kk + tg + 4) * BPITCH + nb];
#pragma unroll
                for (int i = 0; i < 2; i++)
                    mma_tf32(acc[i][j], af[i], b0, b1);
            }
        }
        if (it + 1 < niter) store_smem((it + 1) & 1);
    }

#pragma unroll
    for (int i = 0; i < 2; i++) {
        int r0 = m0 + warp_m * 32 + i * 16 + gp;
        int r1 = r0 + 8;
#pragma unroll
        for (int j = 0; j < 8; j++) {
            int col = warp_n * 64 + j * 8 + tg * 2;
            if (r0 < M)
                *(__half2*)(C + (size_t)r0 * 128 + col) =
                    __floats2half2_rn(acc[i][j][0], acc[i][j][1]);
            if (r1 < M)
                *(__half2*)(C + (size_t)r1 * 128 + col) =
                    __floats2half2_rn(acc[i][j][2], acc[i][j][3]);
        }
    }
}

// ---------------------------------------------------------------------------
// CSR aggregation + bias + erf-GELU, one warp per destination node.
// h is fp16; accumulation in fp32. Inner edge loop unrolled x4 so four
// independent row-gathers are in flight per warp (MLP=4).
// out[d,:] = gelu( h[d,:]*dinv[d]^2 + sum_e h[src_e,:]*coef_e + bias )
// ---------------------------------------------------------------------------
__device__ __forceinline__ float gelu_erf(float x) {
    return 0.5f * x * (1.0f + erff(x * 0.70710678118654752440f));
}

__device__ __forceinline__ float4 load_h4(const __half* __restrict__ h,
                                          size_t row, int lane) {
    float2 raw = ((const float2*)(h + row * 128))[lane];   // 8B = 4 halves
    __half2 p0 = *(__half2*)&raw.x;
    __half2 p1 = *(__half2*)&raw.y;
    float2 f0 = __half22float2(p0);
    float2 f1 = __half22float2(p1);
    return make_float4(f0.x, f0.y, f1.x, f1.y);
}

__global__ __launch_bounds__(256, 8)
void k_aggregate(const int* __restrict__ rowptr, const int* __restrict__ srcs,
                 const float* __restrict__ coefs, const __half* __restrict__ h,
                 const float* __restrict__ dinv, const float* __restrict__ bias,
                 float* __restrict__ out, int n) {
    int node = (blockIdx.x * blockDim.x + threadIdx.x) >> 5;
    int lane = threadIdx.x & 31;
    if (node >= n) return;

    int beg = __ldg(&rowptr[node]);
    int end = __ldg(&rowptr[node + 1]);

    float d = __ldg(&dinv[node]);
    float c = d * d;
    float4 acc = load_h4(h, (size_t)node, lane);
    acc.x *= c; acc.y *= c; acc.z *= c; acc.w *= c;

    for (int base = beg; base < end; base += 32) {
        int m = end - base;
        if (m > 32) m = 32;
        int   s_l = (lane < m) ? __ldg(&srcs[base + lane])  : 0;
        float w_l = (lane < m) ? __ldg(&coefs[base + lane]) : 0.0f;

        int j = 0;
        for (; j + 4 <= m; j += 4) {
            int   s0 = __shfl_sync(0xffffffffu, s_l, j    );
            int   s1 = __shfl_sync(0xffffffffu, s_l, j + 1);
            int   s2 = __shfl_sync(0xffffffffu, s_l, j + 2);
            int   s3 = __shfl_sync(0xffffffffu, s_l, j + 3);
            float w0 = __shfl_sync(0xffffffffu, w_l, j    );
            float w1 = __shfl_sync(0xffffffffu, w_l, j + 1);
            float w2 = __shfl_sync(0xffffffffu, w_l, j + 2);
            float w3 = __shfl_sync(0xffffffffu, w_l, j + 3);
            // four independent gathers -> 4 loads in flight
            float4 v0 = load_h4(h, (size_t)s0, lane);
            float4 v1 = load_h4(h, (size_t)s1, lane);
            float4 v2 = load_h4(h, (size_t)s2, lane);
            float4 v3 = load_h4(h, (size_t)s3, lane);
            acc.x = fmaf(v0.x, w0, acc.x); acc.y = fmaf(v0.y, w0, acc.y);
            acc.z = fmaf(v0.z, w0, acc.z); acc.w = fmaf(v0.w, w0, acc.w);
            acc.x = fmaf(v1.x, w1, acc.x); acc.y = fmaf(v1.y, w1, acc.y);
            acc.z = fmaf(v1.z, w1, acc.z); acc.w = fmaf(v1.w, w1, acc.w);
            acc.x = fmaf(v2.x, w2, acc.x); acc.y = fmaf(v2.y, w2, acc.y);
            acc.z = fmaf(v2.z, w2, acc.z); acc.w = fmaf(v2.w, w2, acc.w);
            acc.x = fmaf(v3.x, w3, acc.x); acc.y = fmaf(v3.y, w3, acc.y);
            acc.z = fmaf(v3.z, w3, acc.z); acc.w = fmaf(v3.w, w3, acc.w);
        }
        for (; j < m; j++) {
            int   s = __shfl_sync(0xffffffffu, s_l, j);
            float w = __shfl_sync(0xffffffffu, w_l, j);
            float4 v = load_h4(h, (size_t)s, lane);
            acc.x = fmaf(v.x, w, acc.x);
            acc.y = fmaf(v.y, w, acc.y);
            acc.z = fmaf(v.z, w, acc.z);
            acc.w = fmaf(v.w, w, acc.w);
        }
    }

    float4 bb = ((const float4*)bias)[lane];
    acc.x = gelu_erf(acc.x + bb.x);
    acc.y = gelu_erf(acc.y + bb.y);
    acc.z = gelu_erf(acc.z + bb.z);
    acc.w = gelu_erf(acc.w + bb.w);
    ((float4*)(out + (size_t)node * 128))[lane] = acc;
}

// ---------------------------------------------------------------------------
// Launch
// ---------------------------------------------------------------------------
extern "C" void kernel_launch(void* const* d_in, const int* in_sizes, int n_in,
                              void* d_out, int out_size) {
    const float* x  = (const float*)d_in[0];
    const int*   ei = (const int*)  d_in[1];
    const float* ew = (const float*)d_in[2];
    const float* W1 = (const float*)d_in[3];
    const float* b1 = (const float*)d_in[4];
    const float* W2 = (const float*)d_in[5];
    const float* b2 = (const float*)d_in[6];
    float* out = (float*)d_out;

    const int n  = out_size / FDIM;       // 100000
    const int K1 = in_sizes[0] / n;       // 256
    const int E  = in_sizes[2];           // 1600000
    const int* src = ei;
    const int* dst = ei + E;

    float *deg, *dinv, *coefs, *a;
    __half* h;
    int *cnt, *rowptr, *cursor, *srcs, *bsum;
    cudaGetSymbolAddress((void**)&deg,    g_deg);
    cudaGetSymbolAddress((void**)&dinv,   g_dinv);
    cudaGetSymbolAddress((void**)&cnt,    g_cnt);
    cudaGetSymbolAddress((void**)&rowptr, g_rowptr);
    cudaGetSymbolAddress((void**)&cursor, g_cursor);
    cudaGetSymbolAddress((void**)&srcs,   g_srcs);
    cudaGetSymbolAddress((void**)&coefs,  g_coefs);
    cudaGetSymbolAddress((void**)&h,      g_h);
    cudaGetSymbolAddress((void**)&a,      g_a);
    cudaGetSymbolAddress((void**)&bsum,   g_bsum);

    const int TB = 256;
    const int nblk = (n + SCAN_TB - 1) / SCAN_TB;
    dim3 gn((n + TB - 1) / TB);
    dim3 ge((E + TB - 1) / TB);
    dim3 gagg(((size_t)n * 32 + TB - 1) / TB);
    dim3 ggemm((n + 127) / 128);

    // --- CSR-by-dst build + normalization (shared by both layers) ---
    k_init      <<<gn, TB>>>(deg, cnt, n);
    k_deg_cnt   <<<ge, TB>>>(dst, ew, deg, cnt, E);
    k_dinv      <<<gn, TB>>>(deg, dinv, n);
    k_reduce    <<<nblk, SCAN_TB>>>(cnt, bsum, n);
    k_scan_sums <<<1, SCAN_TB>>>(bsum, nblk, rowptr, n, E);
    k_scan_final<<<nblk, SCAN_TB>>>(cnt, bsum, rowptr, cursor, n);
    k_fill      <<<ge, TB>>>(src, dst, ew, dinv, cursor, srcs, coefs, E);

    // --- layer 1: h = x@W1 (fp16) ; a = gelu(agg(h) + b1) ---
    k_gemm_mma <<<ggemm, 256>>>(x, W1, h, n, K1);
    k_aggregate<<<gagg, TB>>>(rowptr, srcs, coefs, h, dinv, b1, a, n);

    // --- layer 2: h = a@W2 (fp16) ; out = gelu(agg(h) + b2) ---
    k_gemm_mma <<<ggemm, 256>>>(a, W2, h, n, FDIM);
    k_aggregate<<<gagg, TB>>>(rowptr, srcs, coefs, h, dinv, b2, out, n);
}

// round 8
// speedup vs baseline: 3.1539x; 1.0489x over previous
#include <cuda_runtime.h>
#include <cuda_fp16.h>
#include <math.h>
#include <stdint.h>

// ---------------------------------------------------------------------------
// Problem constants: N=100000 nodes, E=1600000 edges, dims 256 -> 128 -> 128.
// ---------------------------------------------------------------------------
#define NMAX 100000
#define EMAX 1600000
#define FDIM 128
#define SCAN_TB 1024
#define NSCAN_BLOCKS ((NMAX + SCAN_TB - 1) / SCAN_TB)   // 98

// Scratch (static device globals; no runtime allocation).
__device__ float  g_deg   [NMAX];
__device__ float  g_dinv  [NMAX];
__device__ int    g_cnt   [NMAX];
__device__ int    g_rowptr[NMAX + 1];
__device__ int    g_cursor[NMAX];
__device__ int    g_bsum  [NSCAN_BLOCKS];
__device__ int    g_srcs  [EMAX];     // CSR-by-dst: source node per slot
__device__ float  g_coefs [EMAX];     // CSR-by-dst: edge coefficient per slot
__device__ __half g_h     [(size_t)NMAX * FDIM];  // GEMM output (fp16 storage)
__device__ float  g_a     [(size_t)NMAX * FDIM];  // layer-1 activation (fp32)

// ---------------------------------------------------------------------------
// Degree / counts
// ---------------------------------------------------------------------------
__global__ void k_init(float* deg, int* cnt, int n) {
    int i = blockIdx.x * blockDim.x + threadIdx.x;
    if (i < n) { deg[i] = 1.0f; cnt[i] = 0; }
}

__global__ void k_deg_cnt(const int* __restrict__ dst, const float* __restrict__ w,
                          float* deg, int* cnt, int E) {
    int e = blockIdx.x * blockDim.x + threadIdx.x;
    if (e < E) {
        int d = dst[e];
        atomicAdd(&deg[d], w[e]);
        atomicAdd(&cnt[d], 1);
    }
}

__global__ void k_dinv(const float* __restrict__ deg, float* dinv, int n) {
    int i = blockIdx.x * blockDim.x + threadIdx.x;
    if (i < n) dinv[i] = rsqrtf(deg[i]);
}

// ---------------------------------------------------------------------------
// Device-wide exclusive scan of cnt -> rowptr (3 kernels, fully parallel).
// ---------------------------------------------------------------------------
__global__ __launch_bounds__(SCAN_TB)
void k_reduce(const int* __restrict__ cnt, int* __restrict__ bsum, int n) {
    __shared__ int wsum[32];
    int i = blockIdx.x * SCAN_TB + threadIdx.x;
    int v = (i < n) ? cnt[i] : 0;
#pragma unroll
    for (int d = 16; d > 0; d >>= 1) v += __shfl_down_sync(0xffffffffu, v, d);
    int lane = threadIdx.x & 31, wid = threadIdx.x >> 5;
    if (lane == 0) wsum[wid] = v;
    __syncthreads();
    if (wid == 0) {
        int s = wsum[lane];
#pragma unroll
        for (int d = 16; d > 0; d >>= 1) s += __shfl_down_sync(0xffffffffu, s, d);
        if (lane == 0) bsum[blockIdx.x] = s;
    }
}

__global__ __launch_bounds__(SCAN_TB)
void k_scan_sums(int* __restrict__ bsum, int nblk, int* __restrict__ rowptr,
                 int n, int E) {
    __shared__ int wsum[32];
    const int tid = threadIdx.x, lane = tid & 31, wid = tid >> 5;
    int v = (tid < nblk) ? bsum[tid] : 0;
    int x = v;
#pragma unroll
    for (int d = 1; d < 32; d <<= 1) {
        int y = __shfl_up_sync(0xffffffffu, x, d);
        if (lane >= d) x += y;
    }
    if (lane == 31) wsum[wid] = x;
    __syncthreads();
    if (wid == 0) {
        int s = wsum[lane];
#pragma unroll
        for (int d = 1; d < 32; d <<= 1) {
            int y = __shfl_up_sync(0xffffffffu, s, d);
            if (lane >= d) s += y;
        }
        wsum[lane] = s;
    }
    __syncthreads();
    int woff = wid ? wsum[wid - 1] : 0;
    if (tid < nblk) bsum[tid] = woff + x - v;   // exclusive
    if (tid == 0) rowptr[n] = E;
}

__global__ __launch_bounds__(SCAN_TB)
void k_scan_final(const int* __restrict__ cnt, const int* __restrict__ bsum,
                  int* __restrict__ rowptr, int* __restrict__ cursor, int n) {
    __shared__ int wsum[32];
    const int tid = threadIdx.x, lane = tid & 31, wid = tid >> 5;
    int i = blockIdx.x * SCAN_TB + tid;
    int v = (i < n) ? cnt[i] : 0;
    int x = v;
#pragma unroll
    for (int d = 1; d < 32; d <<= 1) {
        int y = __shfl_up_sync(0xffffffffu, x, d);
        if (lane >= d) x += y;
    }
    if (lane == 31) wsum[wid] = x;
    __syncthreads();
    if (wid == 0) {
        int s = wsum[lane];
#pragma unroll
        for (int d = 1; d < 32; d <<= 1) {
            int y = __shfl_up_sync(0xffffffffu, s, d);
            if (lane >= d) s += y;
        }
        wsum[lane] = s;
    }
    __syncthreads();
    int woff = wid ? wsum[wid - 1] : 0;
    if (i < n) {
        int r = bsum[blockIdx.x] + woff + x - v;
        rowptr[i] = r;
        cursor[i] = r;
    }
}

// Fill CSR slots; also computes the per-edge GCN coefficient.
__global__ void k_fill(const int* __restrict__ src, const int* __restrict__ dst,
                       const float* __restrict__ w, const float* __restrict__ dinv,
                       int* cursor, int* __restrict__ srcs, float* __restrict__ coefs,
                       int E) {
    int e = blockIdx.x * blockDim.x + threadIdx.x;
    if (e >= E) return;
    int s = src[e], d = dst[e];
    int pos = atomicAdd(&cursor[d], 1);
    srcs[pos]  = s;
    coefs[pos] = dinv[s] * w[e] * dinv[d];
}

// ---------------------------------------------------------------------------
// tf32 mma.sync GEMM: C[M,128] = A[M,K] @ B[K,128], epilogue stores fp16.
// CTA tile 128x128, BK=16, 8 warps, warp tile 32x64, m16n8k8, fp32 acc.
// ---------------------------------------------------------------------------
#define APITCH 20
#define BPITCH 136

__device__ __forceinline__ uint32_t f2tf32(float x) {
    uint32_t r;
    asm("cvt.rna.tf32.f32 %0, %1;" : "=r"(r) : "f"(x));
    return r;
}

__device__ __forceinline__ void mma_tf32(float* c, const uint32_t* a,
                                         uint32_t b0, uint32_t b1) {
    asm volatile(
        "mma.sync.aligned.m16n8k8.row.col.f32.tf32.tf32.f32 "
        "{%0,%1,%2,%3}, {%4,%5,%6,%7}, {%8,%9}, {%0,%1,%2,%3};"
        : "+f"(c[0]), "+f"(c[1]), "+f"(c[2]), "+f"(c[3])
        : "r"(a[0]), "r"(a[1]), "r"(a[2]), "r"(a[3]), "r"(b0), "r"(b1));
}

__global__ __launch_bounds__(256, 2)
void k_gemm_mma(const float* __restrict__ A, const float* __restrict__ B,
                __half* __restrict__ C, int M, int K) {
    __shared__ __align__(16) float As[2][128 * APITCH];
    __shared__ __align__(16) float Bs[2][16 * BPITCH];

    const int tid  = threadIdx.x;
    const int lane = tid & 31;
    const int wid  = tid >> 5;
    const int warp_m = wid & 3;
    const int warp_n = wid >> 2;
    const int gp = lane >> 2;
    const int tg = lane & 3;
    const int m0 = blockIdx.x * 128;

    float acc[2][8][4];
#pragma unroll
    for (int i = 0; i < 2; i++)
#pragma unroll
        for (int j = 0; j < 8; j++)
#pragma unroll
            for (int q = 0; q < 4; q++) acc[i][j][q] = 0.0f;

    float4 pa[2], pb[2];

    auto load_regs = [&](int k0) {
#pragma unroll
        for (int u = 0; u < 2; u++) {
            int idx = tid + u * 256;
            int ar  = idx >> 2;
            int aq  = idx & 3;
            pa[u] = (m0 + ar < M)
                  ? *(const float4*)(A + (size_t)(m0 + ar) * K + k0 + aq * 4)
                  : make_float4(0.f, 0.f, 0.f, 0.f);
            int kr = idx >> 5;
            int bq = idx & 31;
            pb[u] = *(const float4*)(B + (size_t)(k0 + kr) * 128 + bq * 4);
        }
    };

    auto store_smem = [&](int buf) {
#pragma unroll
        for (int u = 0; u < 2; u++) {
            int idx = tid + u * 256;
            int ar  = idx >> 2;
            int aq  = idx & 3;
            uint32_t* d = (uint32_t*)&As[buf][ar * APITCH + aq * 4];
            d[0] = f2tf32(pa[u].x); d[1] = f2tf32(pa[u].y);
            d[2] = f2tf32(pa[u].z); d[3] = f2tf32(pa[u].w);
            int kr = idx >> 5;
            int bq = idx & 31;
            uint32_t* e = (uint32_t*)&Bs[buf][kr * BPITCH + bq * 4];
            e[0] = f2tf32(pb[u].x); e[1] = f2tf32(pb[u].y);
            e[2] = f2tf32(pb[u].z); e[3] = f2tf32(pb[u].w);
        }
    };

    const int niter = K / 16;
    load_regs(0);
    store_smem(0);

    for (int it = 0; it < niter; it++) {
        if (it + 1 < niter) load_regs((it + 1) * 16);
        __syncthreads();
        const int buf = it & 1;
        const uint32_t* as = (const uint32_t*)&As[buf][0];
        const uint32_t* bs = (const uint32_t*)&Bs[buf][0];

#pragma unroll
        for (int kk = 0; kk < 16; kk += 8) {
            uint32_t af[2][4];
#pragma unroll
            for (int i = 0; i < 2; i++) {
                int mr = warp_m * 32 + i * 16 + gp;
                af[i][0] = as[(mr    ) * APITCH + kk + tg    ];
                af[i][1] = as[(mr + 8) * APITCH + kk + tg    ];
                af[i][2] = as[(mr    ) * APITCH + kk + tg + 4];
                af[i][3] = as[(mr + 8) * APITCH + kk + tg + 4];
            }
#pragma unroll
            for (int j = 0; j < 8; j++) {
                int nb = warp_n * 64 + j * 8 + gp;
                uint32_t b0 = bs[(kk + tg    ) * BPITCH + nb];
                uint32_t b1 = bs[(kk + tg + 4) * BPITCH + nb];
#pragma unroll
                for (int i = 0; i < 2; i++)
                    mma_tf32(acc[i][j], af[i], b0, b1);
            }
        }
        if (it + 1 < niter) store_smem((it + 1) & 1);
    }

#pragma unroll
    for (int i = 0; i < 2; i++) {
        int r0 = m0 + warp_m * 32 + i * 16 + gp;
        int r1 = r0 + 8;
#pragma unroll
        for (int j = 0; j < 8; j++) {
            int col = warp_n * 64 + j * 8 + tg * 2;
            if (r0 < M)
                *(__half2*)(C + (size_t)r0 * 128 + col) =
                    __floats2half2_rn(acc[i][j][0], acc[i][j][1]);
            if (r1 < M)
                *(__half2*)(C + (size_t)r1 * 128 + col) =
                    __floats2half2_rn(acc[i][j][2], acc[i][j][3]);
        }
    }
}

// ---------------------------------------------------------------------------
// CSR aggregation + bias + erf-GELU, one warp per destination node.
// h is fp16; accumulation in fp32. Inner edge loop unrolled x4 (MLP=4).
// out[d,:] = gelu( h[d,:]*dinv[d]^2 + sum_e h[src_e,:]*coef_e + bias )
// ---------------------------------------------------------------------------
__device__ __forceinline__ float gelu_erf(float x) {
    return 0.5f * x * (1.0f + erff(x * 0.70710678118654752440f));
}

__device__ __forceinline__ float4 load_h4(const __half* __restrict__ h,
                                          size_t row, int lane) {
    float2 raw = ((const float2*)(h + row * 128))[lane];   // 8B = 4 halves
    __half2 p0 = *(__half2*)&raw.x;
    __half2 p1 = *(__half2*)&raw.y;
    float2 f0 = __half22float2(p0);
    float2 f1 = __half22float2(p1);
    return make_float4(f0.x, f0.y, f1.x, f1.y);
}

__global__ __launch_bounds__(256, 8)
void k_aggregate(const int* __restrict__ rowptr, const int* __restrict__ srcs,
                 const float* __restrict__ coefs, const __half* __restrict__ h,
                 const float* __restrict__ dinv, const float* __restrict__ bias,
                 float* __restrict__ out, int n) {
    int node = (blockIdx.x * blockDim.x + threadIdx.x) >> 5;
    int lane = threadIdx.x & 31;
    if (node >= n) return;

    int beg = __ldg(&rowptr[node]);
    int end = __ldg(&rowptr[node + 1]);

    float d = __ldg(&dinv[node]);
    float c = d * d;
    float4 acc = load_h4(h, (size_t)node, lane);
    acc.x *= c; acc.y *= c; acc.z *= c; acc.w *= c;

    for (int base = beg; base < end; base += 32) {
        int m = end - base;
        if (m > 32) m = 32;
        int   s_l = (lane < m) ? __ldg(&srcs[base + lane])  : 0;
        float w_l = (lane < m) ? __ldg(&coefs[base + lane]) : 0.0f;

        int j = 0;
        for (; j + 4 <= m; j += 4) {
            int   s0 = __shfl_sync(0xffffffffu, s_l, j    );
            int   s1 = __shfl_sync(0xffffffffu, s_l, j + 1);
            int   s2 = __shfl_sync(0xffffffffu, s_l, j + 2);
            int   s3 = __shfl_sync(0xffffffffu, s_l, j + 3);
            float w0 = __shfl_sync(0xffffffffu, w_l, j    );
            float w1 = __shfl_sync(0xffffffffu, w_l, j + 1);
            float w2 = __shfl_sync(0xffffffffu, w_l, j + 2);
            float w3 = __shfl_sync(0xffffffffu, w_l, j + 3);
            float4 v0 = load_h4(h, (size_t)s0, lane);
            float4 v1 = load_h4(h, (size_t)s1, lane);
            float4 v2 = load_h4(h, (size_t)s2, lane);
            float4 v3 = load_h4(h, (size_t)s3, lane);
            acc.x = fmaf(v0.x, w0, acc.x); acc.y = fmaf(v0.y, w0, acc.y);
            acc.z = fmaf(v0.z, w0, acc.z); acc.w = fmaf(v0.w, w0, acc.w);
            acc.x = fmaf(v1.x, w1, acc.x); acc.y = fmaf(v1.y, w1, acc.y);
            acc.z = fmaf(v1.z, w1, acc.z); acc.w = fmaf(v1.w, w1, acc.w);
            acc.x = fmaf(v2.x, w2, acc.x); acc.y = fmaf(v2.y, w2, acc.y);
            acc.z = fmaf(v2.z, w2, acc.z); acc.w = fmaf(v2.w, w2, acc.w);
            acc.x = fmaf(v3.x, w3, acc.x); acc.y = fmaf(v3.y, w3, acc.y);
            acc.z = fmaf(v3.z, w3, acc.z); acc.w = fmaf(v3.w, w3, acc.w);
        }
        for (; j < m; j++) {
            int   s = __shfl_sync(0xffffffffu, s_l, j);
            float w = __shfl_sync(0xffffffffu, w_l, j);
            float4 v = load_h4(h, (size_t)s, lane);
            acc.x = fmaf(v.x, w, acc.x);
            acc.y = fmaf(v.y, w, acc.y);
            acc.z = fmaf(v.z, w, acc.z);
            acc.w = fmaf(v.w, w, acc.w);
        }
    }

    float4 bb = ((const float4*)bias)[lane];
    acc.x = gelu_erf(acc.x + bb.x);
    acc.y = gelu_erf(acc.y + bb.y);
    acc.z = gelu_erf(acc.z + bb.z);
    acc.w = gelu_erf(acc.w + bb.w);
    ((float4*)(out + (size_t)node * 128))[lane] = acc;
}

// ---------------------------------------------------------------------------
// Launch. Graph topology:
//   default stream:  [fork] GEMM1 ----------------[join] agg1  GEMM2  agg2
//   side stream s2:  [fork] init deg dinv scan fill [join]
// The CSR build (depends only on edges/weights) overlaps GEMM1 (x @ W1).
// Host code runs only on the correctness call and the capture call, so
// creating the stream/events per call leaks nothing at replay time.
// ---------------------------------------------------------------------------
extern "C" void kernel_launch(void* const* d_in, const int* in_sizes, int n_in,
                              void* d_out, int out_size) {
    const float* x  = (const float*)d_in[0];
    const int*   ei = (const int*)  d_in[1];
    const float* ew = (const float*)d_in[2];
    const float* W1 = (const float*)d_in[3];
    const float* b1 = (const float*)d_in[4];
    const float* W2 = (const float*)d_in[5];
    const float* b2 = (const float*)d_in[6];
    float* out = (float*)d_out;

    const int n  = out_size / FDIM;       // 100000
    const int K1 = in_sizes[0] / n;       // 256
    const int E  = in_sizes[2];           // 1600000
    const int* src = ei;
    const int* dst = ei + E;

    float *deg, *dinv, *coefs, *a;
    __half* h;
    int *cnt, *rowptr, *cursor, *srcs, *bsum;
    cudaGetSymbolAddress((void**)&deg,    g_deg);
    cudaGetSymbolAddress((void**)&dinv,   g_dinv);
    cudaGetSymbolAddress((void**)&cnt,    g_cnt);
    cudaGetSymbolAddress((void**)&rowptr, g_rowptr);
    cudaGetSymbolAddress((void**)&cursor, g_cursor);
    cudaGetSymbolAddress((void**)&srcs,   g_srcs);
    cudaGetSymbolAddress((void**)&coefs,  g_coefs);
    cudaGetSymbolAddress((void**)&h,      g_h);
    cudaGetSymbolAddress((void**)&a,      g_a);
    cudaGetSymbolAddress((void**)&bsum,   g_bsum);

    const int TB = 256;
    const int nblk = (n + SCAN_TB - 1) / SCAN_TB;
    dim3 gn((n + TB - 1) / TB);
    dim3 ge((E + TB - 1) / TB);
    dim3 gagg(((size_t)n * 32 + TB - 1) / TB);
    dim3 ggemm((n + 127) / 128);

    // Fork a side stream off the (capturing) default stream.
    cudaStream_t s2;
    cudaEvent_t evFork, evJoin;
    cudaStreamCreateWithFlags(&s2, cudaStreamNonBlocking);
    cudaEventCreateWithFlags(&evFork, cudaEventDisableTiming);
    cudaEventCreateWithFlags(&evJoin, cudaEventDisableTiming);

    cudaEventRecord(evFork, 0);
    cudaStreamWaitEvent(s2, evFork, 0);

    // --- side stream: CSR-by-dst build + normalization ---
    k_init      <<<gn, TB, 0, s2>>>(deg, cnt, n);
    k_deg_cnt   <<<ge, TB, 0, s2>>>(dst, ew, deg, cnt, E);
    k_dinv      <<<gn, TB, 0, s2>>>(deg, dinv, n);
    k_reduce    <<<nblk, SCAN_TB, 0, s2>>>(cnt, bsum, n);
    k_scan_sums <<<1, SCAN_TB, 0, s2>>>(bsum, nblk, rowptr, n, E);
    k_scan_final<<<nblk, SCAN_TB, 0, s2>>>(cnt, bsum, rowptr, cursor, n);
    k_fill      <<<ge, TB, 0, s2>>>(src, dst, ew, dinv, cursor, srcs, coefs, E);
    cudaEventRecord(evJoin, s2);

    // --- default stream: GEMM1 runs concurrently with the CSR build ---
    k_gemm_mma <<<ggemm, 256>>>(x, W1, h, n, K1);

    // join: aggregation needs both GEMM1 output and the CSR structure
    cudaStreamWaitEvent(0, evJoin, 0);

    // --- layer 1 aggregate, then layer 2 (serial dependency chain) ---
    k_aggregate<<<gagg, TB>>>(rowptr, srcs, coefs, h, dinv, b1, a, n);
    k_gemm_mma <<<ggemm, 256>>>(a, W2, h, n, FDIM);
    k_aggregate<<<gagg, TB>>>(rowptr, srcs, coefs, h, dinv, b2, out, n);
}

// round 9
// speedup vs baseline: 3.2428x; 1.0282x over previous
#include <cuda_runtime.h>
#include <cuda_fp16.h>
#include <math.h>
#include <stdint.h>

// ---------------------------------------------------------------------------
// Problem constants: N=100000 nodes, E=1600000 edges, dims 256 -> 128 -> 128.
// ---------------------------------------------------------------------------
#define NMAX 100000
#define EMAX 1600000
#define FDIM 128
#define SCAN_TB 1024
#define NSCAN_BLOCKS ((NMAX + SCAN_TB - 1) / SCAN_TB)   // 98

// Scratch (static device globals; no runtime allocation).
__device__ float  g_deg   [NMAX];
__device__ float  g_dinv  [NMAX];
__device__ int    g_cnt   [NMAX];
__device__ int    g_rowptr[NMAX + 1];
__device__ int    g_cursor[NMAX];
__device__ int    g_bsum  [NSCAN_BLOCKS];
__device__ int2   g_edge  [EMAX];    // CSR-by-dst: {src, coef-as-bits} per slot
__device__ __half g_h     [(size_t)NMAX * FDIM];  // GEMM output (fp16)
__device__ __half g_a     [(size_t)NMAX * FDIM];  // layer-1 activation (fp16)

// ---------------------------------------------------------------------------
// Degree / counts
// ---------------------------------------------------------------------------
__global__ void k_init(float* deg, int* cnt, int n) {
    int i = blockIdx.x * blockDim.x + threadIdx.x;
    if (i < n) { deg[i] = 1.0f; cnt[i] = 0; }
}

__global__ void k_deg_cnt(const int* __restrict__ dst, const float* __restrict__ w,
                          float* deg, int* cnt, int E) {
    int e = blockIdx.x * blockDim.x + threadIdx.x;
    if (e < E) {
        int d = dst[e];
        atomicAdd(&deg[d], w[e]);
        atomicAdd(&cnt[d], 1);
    }
}

__global__ void k_dinv(const float* __restrict__ deg, float* dinv, int n) {
    int i = blockIdx.x * blockDim.x + threadIdx.x;
    if (i < n) dinv[i] = rsqrtf(deg[i]);
}

// ---------------------------------------------------------------------------
// Device-wide exclusive scan of cnt -> rowptr (3 kernels, fully parallel).
// ---------------------------------------------------------------------------
__global__ __launch_bounds__(SCAN_TB)
void k_reduce(const int* __restrict__ cnt, int* __restrict__ bsum, int n) {
    __shared__ int wsum[32];
    int i = blockIdx.x * SCAN_TB + threadIdx.x;
    int v = (i < n) ? cnt[i] : 0;
#pragma unroll
    for (int d = 16; d > 0; d >>= 1) v += __shfl_down_sync(0xffffffffu, v, d);
    int lane = threadIdx.x & 31, wid = threadIdx.x >> 5;
    if (lane == 0) wsum[wid] = v;
    __syncthreads();
    if (wid == 0) {
        int s = wsum[lane];
#pragma unroll
        for (int d = 16; d > 0; d >>= 1) s += __shfl_down_sync(0xffffffffu, s, d);
        if (lane == 0) bsum[blockIdx.x] = s;
    }
}

__global__ __launch_bounds__(SCAN_TB)
void k_scan_sums(int* __restrict__ bsum, int nblk, int* __restrict__ rowptr,
                 int n, int E) {
    __shared__ int wsum[32];
    const int tid = threadIdx.x, lane = tid & 31, wid = tid >> 5;
    int v = (tid < nblk) ? bsum[tid] : 0;
    int x = v;
#pragma unroll
    for (int d = 1; d < 32; d <<= 1) {
        int y = __shfl_up_sync(0xffffffffu, x, d);
        if (lane >= d) x += y;
    }
    if (lane == 31) wsum[wid] = x;
    __syncthreads();
    if (wid == 0) {
        int s = wsum[lane];
#pragma unroll
        for (int d = 1; d < 32; d <<= 1) {
            int y = __shfl_up_sync(0xffffffffu, s, d);
            if (lane >= d) s += y;
        }
        wsum[lane] = s;
    }
    __syncthreads();
    int woff = wid ? wsum[wid - 1] : 0;
    if (tid < nblk) bsum[tid] = woff + x - v;   // exclusive
    if (tid == 0) rowptr[n] = E;
}

__global__ __launch_bounds__(SCAN_TB)
void k_scan_final(const int* __restrict__ cnt, const int* __restrict__ bsum,
                  int* __restrict__ rowptr, int* __restrict__ cursor, int n) {
    __shared__ int wsum[32];
    const int tid = threadIdx.x, lane = tid & 31, wid = tid >> 5;
    int i = blockIdx.x * SCAN_TB + tid;
    int v = (i < n) ? cnt[i] : 0;
    int x = v;
#pragma unroll
    for (int d = 1; d < 32; d <<= 1) {
        int y = __shfl_up_sync(0xffffffffu, x, d);
        if (lane >= d) x += y;
    }
    if (lane == 31) wsum[wid] = x;
    __syncthreads();
    if (wid == 0) {
        int s = wsum[lane];
#pragma unroll
        for (int d = 1; d < 32; d <<= 1) {
            int y = __shfl_up_sync(0xffffffffu, s, d);
            if (lane >= d) s += y;
        }
        wsum[lane] = s;
    }
    __syncthreads();
    int woff = wid ? wsum[wid - 1] : 0;
    if (i < n) {
        int r = bsum[blockIdx.x] + woff + x - v;
        rowptr[i] = r;
        cursor[i] = r;
    }
}

// Fill CSR slots; packs {src, coef} into one 8B record.
__global__ void k_fill(const int* __restrict__ src, const int* __restrict__ dst,
                       const float* __restrict__ w, const float* __restrict__ dinv,
                       int* cursor, int2* __restrict__ edge, int E) {
    int e = blockIdx.x * blockDim.x + threadIdx.x;
    if (e >= E) return;
    int s = src[e], d = dst[e];
    int pos = atomicAdd(&cursor[d], 1);
    float coef = dinv[s] * w[e] * dinv[d];
    edge[pos] = make_int2(s, __float_as_int(coef));
}

// ---------------------------------------------------------------------------
// tf32 mma.sync GEMM: C[M,128] = A[M,K] @ B[K,128], epilogue stores fp16.
// A operand templated: float (layer 1) or __half (layer 2).
// CTA tile 128x128, BK=16, 8 warps, warp tile 32x64, m16n8k8, fp32 acc.
// ---------------------------------------------------------------------------
#define APITCH 20
#define BPITCH 136

__device__ __forceinline__ uint32_t f2tf32(float x) {
    uint32_t r;
    asm("cvt.rna.tf32.f32 %0, %1;" : "=r"(r) : "f"(x));
    return r;
}

__device__ __forceinline__ void mma_tf32(float* c, const uint32_t* a,
                                         uint32_t b0, uint32_t b1) {
    asm volatile(
        "mma.sync.aligned.m16n8k8.row.col.f32.tf32.tf32.f32 "
        "{%0,%1,%2,%3}, {%4,%5,%6,%7}, {%8,%9}, {%0,%1,%2,%3};"
        : "+f"(c[0]), "+f"(c[1]), "+f"(c[2]), "+f"(c[3])
        : "r"(a[0]), "r"(a[1]), "r"(a[2]), "r"(a[3]), "r"(b0), "r"(b1));
}

// 4 consecutive A elements starting at (row, k) -> float4
__device__ __forceinline__ float4 loadA4(const float* A, size_t off) {
    return *(const float4*)(A + off);
}
__device__ __forceinline__ float4 loadA4(const __half* A, size_t off) {
    uint2 raw = *(const uint2*)(A + off);             // 8B = 4 halves
    __half2 p0 = *(__half2*)&raw.x;
    __half2 p1 = *(__half2*)&raw.y;
    float2 f0 = __half22float2(p0);
    float2 f1 = __half22float2(p1);
    return make_float4(f0.x, f0.y, f1.x, f1.y);
}

template <typename AT>
__global__ __launch_bounds__(256, 2)
void k_gemm_mma(const AT* __restrict__ A, const float* __restrict__ B,
                __half* __restrict__ C, int M, int K) {
    __shared__ __align__(16) float As[2][128 * APITCH];
    __shared__ __align__(16) float Bs[2][16 * BPITCH];

    const int tid  = threadIdx.x;
    const int lane = tid & 31;
    const int wid  = tid >> 5;
    const int warp_m = wid & 3;
    const int warp_n = wid >> 2;
    const int gp = lane >> 2;
    const int tg = lane & 3;
    const int m0 = blockIdx.x * 128;

    float acc[2][8][4];
#pragma unroll
    for (int i = 0; i < 2; i++)
#pragma unroll
        for (int j = 0; j < 8; j++)
#pragma unroll
            for (int q = 0; q < 4; q++) acc[i][j][q] = 0.0f;

    float4 pa[2], pb[2];

    auto load_regs = [&](int k0) {
#pragma unroll
        for (int u = 0; u < 2; u++) {
            int idx = tid + u * 256;
            int ar  = idx >> 2;
            int aq  = idx & 3;
            pa[u] = (m0 + ar < M)
                  ? loadA4(A, (size_t)(m0 + ar) * K + k0 + aq * 4)
                  : make_float4(0.f, 0.f, 0.f, 0.f);
            int kr = idx >> 5;
            int bq = idx & 31;
            pb[u] = *(const float4*)(B + (size_t)(k0 + kr) * 128 + bq * 4);
        }
    };

    auto store_smem = [&](int buf) {
#pragma unroll
        for (int u = 0; u < 2; u++) {
            int idx = tid + u * 256;
            int ar  = idx >> 2;
            int aq  = idx & 3;
            uint32_t* d = (uint32_t*)&As[buf][ar * APITCH + aq * 4];
            d[0] = f2tf32(pa[u].x); d[1] = f2tf32(pa[u].y);
            d[2] = f2tf32(pa[u].z); d[3] = f2tf32(pa[u].w);
            int kr = idx >> 5;
            int bq = idx & 31;
            uint32_t* e = (uint32_t*)&Bs[buf][kr * BPITCH + bq * 4];
            e[0] = f2tf32(pb[u].x); e[1] = f2tf32(pb[u].y);
            e[2] = f2tf32(pb[u].z); e[3] = f2tf32(pb[u].w);
        }
    };

    const int niter = K / 16;
    load_regs(0);
    store_smem(0);

    for (int it = 0; it < niter; it++) {
        if (it + 1 < niter) load_regs((it + 1) * 16);
        __syncthreads();
        const int buf = it & 1;
        const uint32_t* as = (const uint32_t*)&As[buf][0];
        const uint32_t* bs = (const uint32_t*)&Bs[buf][0];

#pragma unroll
        for (int kk = 0; kk < 16; kk += 8) {
            uint32_t af[2][4];
#pragma unroll
            for (int i = 0; i < 2; i++) {
                int mr = warp_m * 32 + i * 16 + gp;
                af[i][0] = as[(mr    ) * APITCH + kk + tg    ];
                af[i][1] = as[(mr + 8) * APITCH + kk + tg    ];
                af[i][2] = as[(mr    ) * APITCH + kk + tg + 4];
                af[i][3] = as[(mr + 8) * APITCH + kk + tg + 4];
            }
#pragma unroll
            for (int j = 0; j < 8; j++) {
                int nb = warp_n * 64 + j * 8 + gp;
                uint32_t b0 = bs[(kk + tg    ) * BPITCH + nb];
                uint32_t b1 = bs[(kk + tg + 4) * BPITCH + nb];
#pragma unroll
                for (int i = 0; i < 2; i++)
                    mma_tf32(acc[i][j], af[i], b0, b1);
            }
        }
        if (it + 1 < niter) store_smem((it + 1) & 1);
    }

#pragma unroll
    for (int i = 0; i < 2; i++) {
        int r0 = m0 + warp_m * 32 + i * 16 + gp;
        int r1 = r0 + 8;
#pragma unroll
        for (int j = 0; j < 8; j++) {
            int col = warp_n * 64 + j * 8 + tg * 2;
            if (r0 < M)
                *(__half2*)(C + (size_t)r0 * 128 + col) =
                    __floats2half2_rn(acc[i][j][0], acc[i][j][1]);
            if (r1 < M)
                *(__half2*)(C + (size_t)r1 * 128 + col) =
                    __floats2half2_rn(acc[i][j][2], acc[i][j][3]);
        }
    }
}

// ---------------------------------------------------------------------------
// CSR aggregation + bias + erf-GELU, one warp per destination node.
// h is fp16; accumulation in fp32; output templated (fp16 mid / fp32 final).
// out[d,:] = gelu( h[d,:]*dinv[d]^2 + sum_e h[src_e,:]*coef_e + bias )
// ---------------------------------------------------------------------------
__device__ __forceinline__ float gelu_erf(float x) {
    return 0.5f * x * (1.0f + erff(x * 0.70710678118654752440f));
}

__device__ __forceinline__ float4 load_h4(const __half* __restrict__ h,
                                          size_t row, int lane) {
    float2 raw = ((const float2*)(h + row * 128))[lane];   // 8B = 4 halves
    __half2 p0 = *(__half2*)&raw.x;
    __half2 p1 = *(__half2*)&raw.y;
    float2 f0 = __half22float2(p0);
    float2 f1 = __half22float2(p1);
    return make_float4(f0.x, f0.y, f1.x, f1.y);
}

__device__ __forceinline__ void store_out(float* out, size_t row, int lane, float4 v) {
    ((float4*)(out + row * 128))[lane] = v;
}
__device__ __forceinline__ void store_out(__half* out, size_t row, int lane, float4 v) {
    float2 packed;
    *(__half2*)&packed.x = __floats2half2_rn(v.x, v.y);
    *(__half2*)&packed.y = __floats2half2_rn(v.z, v.w);
    ((float2*)(out + row * 128))[lane] = packed;
}

template <typename OutT>
__global__ __launch_bounds__(256, 8)
void k_aggregate(const int* __restrict__ rowptr, const int2* __restrict__ edge,
                 const __half* __restrict__ h, const float* __restrict__ dinv,
                 const float* __restrict__ bias, OutT* __restrict__ out, int n) {
    int node = (blockIdx.x * blockDim.x + threadIdx.x) >> 5;
    int lane = threadIdx.x & 31;
    if (node >= n) return;

    int beg = __ldg(&rowptr[node]);
    int end = __ldg(&rowptr[node + 1]);

    float d = __ldg(&dinv[node]);
    float c = d * d;
    float4 acc = load_h4(h, (size_t)node, lane);
    acc.x *= c; acc.y *= c; acc.z *= c; acc.w *= c;

    for (int base = beg; base < end; base += 32) {
        int m = end - base;
        if (m > 32) m = 32;
        int2 e_l = (lane < m) ? __ldg(&edge[base + lane]) : make_int2(0, 0);

        int j = 0;
        for (; j + 4 <= m; j += 4) {
            int   s0 = __shfl_sync(0xffffffffu, e_l.x, j    );
            int   s1 = __shfl_sync(0xffffffffu, e_l.x, j + 1);
            int   s2 = __shfl_sync(0xffffffffu, e_l.x, j + 2);
            int   s3 = __shfl_sync(0xffffffffu, e_l.x, j + 3);
            float w0 = __int_as_float(__shfl_sync(0xffffffffu, e_l.y, j    ));
            float w1 = __int_as_float(__shfl_sync(0xffffffffu, e_l.y, j + 1));
            float w2 = __int_as_float(__shfl_sync(0xffffffffu, e_l.y, j + 2));
            float w3 = __int_as_float(__shfl_sync(0xffffffffu, e_l.y, j + 3));
            float4 v0 = load_h4(h, (size_t)s0, lane);
            float4 v1 = load_h4(h, (size_t)s1, lane);
            float4 v2 = load_h4(h, (size_t)s2, lane);
            float4 v3 = load_h4(h, (size_t)s3, lane);
            acc.x = fmaf(v0.x, w0, acc.x); acc.y = fmaf(v0.y, w0, acc.y);
            acc.z = fmaf(v0.z, w0, acc.z); acc.w = fmaf(v0.w, w0, acc.w);
            acc.x = fmaf(v1.x, w1, acc.x); acc.y = fmaf(v1.y, w1, acc.y);
            acc.z = fmaf(v1.z, w1, acc.z); acc.w = fmaf(v1.w, w1, acc.w);
            acc.x = fmaf(v2.x, w2, acc.x); acc.y = fmaf(v2.y, w2, acc.y);
            acc.z = fmaf(v2.z, w2, acc.z); acc.w = fmaf(v2.w, w2, acc.w);
            acc.x = fmaf(v3.x, w3, acc.x); acc.y = fmaf(v3.y, w3, acc.y);
            acc.z = fmaf(v3.z, w3, acc.z); acc.w = fmaf(v3.w, w3, acc.w);
        }
        for (; j < m; j++) {
            int   s = __shfl_sync(0xffffffffu, e_l.x, j);
            float w = __int_as_float(__shfl_sync(0xffffffffu, e_l.y, j));
            float4 v = load_h4(h, (size_t)s, lane);
            acc.x = fmaf(v.x, w, acc.x);
            acc.y = fmaf(v.y, w, acc.y);
            acc.z = fmaf(v.z, w, acc.z);
            acc.w = fmaf(v.w, w, acc.w);
        }
    }

    float4 bb = ((const float4*)bias)[lane];
    acc.x = gelu_erf(acc.x + bb.x);
    acc.y = gelu_erf(acc.y + bb.y);
    acc.z = gelu_erf(acc.z + bb.z);
    acc.w = gelu_erf(acc.w + bb.w);
    store_out(out, (size_t)node, lane, acc);
}

// ---------------------------------------------------------------------------
// Launch. Graph topology:
//   default stream:  [fork] GEMM1 ----------------[join] agg1  GEMM2  agg2
//   side stream s2:  [fork] init deg dinv scan fill [join]
// ---------------------------------------------------------------------------
extern "C" void kernel_launch(void* const* d_in, const int* in_sizes, int n_in,
                              void* d_out, int out_size) {
    const float* x  = (const float*)d_in[0];
    const int*   ei = (const int*)  d_in[1];
    const float* ew = (const float*)d_in[2];
    const float* W1 = (const float*)d_in[3];
    const float* b1 = (const float*)d_in[4];
    const float* W2 = (const float*)d_in[5];
    const float* b2 = (const float*)d_in[6];
    float* out = (float*)d_out;

    const int n  = out_size / FDIM;       // 100000
    const int K1 = in_sizes[0] / n;       // 256
    const int E  = in_sizes[2];           // 1600000
    const int* src = ei;
    const int* dst = ei + E;

    float *deg, *dinv;
    __half *h, *a;
    int *cnt, *rowptr, *cursor, *bsum;
    int2* edge;
    cudaGetSymbolAddress((void**)&deg,    g_deg);
    cudaGetSymbolAddress((void**)&dinv,   g_dinv);
    cudaGetSymbolAddress((void**)&cnt,    g_cnt);
    cudaGetSymbolAddress((void**)&rowptr, g_rowptr);
    cudaGetSymbolAddress((void**)&cursor, g_cursor);
    cudaGetSymbolAddress((void**)&edge,   g_edge);
    cudaGetSymbolAddress((void**)&h,      g_h);
    cudaGetSymbolAddress((void**)&a,      g_a);
    cudaGetSymbolAddress((void**)&bsum,   g_bsum);

    const int TB = 256;
    const int nblk = (n + SCAN_TB - 1) / SCAN_TB;
    dim3 gn((n + TB - 1) / TB);
    dim3 ge((E + TB - 1) / TB);
    dim3 gagg(((size_t)n * 32 + TB - 1) / TB);
    dim3 ggemm((n + 127) / 128);

    cudaStream_t s2;
    cudaEvent_t evFork, evJoin;
    cudaStreamCreateWithFlags(&s2, cudaStreamNonBlocking);
    cudaEventCreateWithFlags(&evFork, cudaEventDisableTiming);
    cudaEventCreateWithFlags(&evJoin, cudaEventDisableTiming);

    cudaEventRecord(evFork, 0);
    cudaStreamWaitEvent(s2, evFork, 0);

    // --- side stream: CSR-by-dst build + normalization ---
    k_init      <<<gn, TB, 0, s2>>>(deg, cnt, n);
    k_deg_cnt   <<<ge, TB, 0, s2>>>(dst, ew, deg, cnt, E);
    k_dinv      <<<gn, TB, 0, s2>>>(deg, dinv, n);
    k_reduce    <<<nblk, SCAN_TB, 0, s2>>>(cnt, bsum, n);
    k_scan_sums <<<1, SCAN_TB, 0, s2>>>(bsum, nblk, rowptr, n, E);
    k_scan_final<<<nblk, SCAN_TB, 0, s2>>>(cnt, bsum, rowptr, cursor, n);
    k_fill      <<<ge, TB, 0, s2>>>(src, dst, ew, dinv, cursor, edge, E);
    cudaEventRecord(evJoin, s2);

    // --- default stream: GEMM1 runs concurrently with the CSR build ---
    k_gemm_mma<float><<<ggemm, 256>>>(x, W1, h, n, K1);

    cudaStreamWaitEvent(0, evJoin, 0);

    // --- layer 1 aggregate (fp16 out), layer 2 GEMM (fp16 A), final agg ---
    k_aggregate<__half><<<gagg, TB>>>(rowptr, edge, h, dinv, b1, a, n);
    k_gemm_mma<__half><<<ggemm, 256>>>(a, W2, h, n, FDIM);
    k_aggregate<float> <<<gagg, TB>>>(rowptr, edge, h, dinv, b2, out, n);
}

// round 10
// speedup vs baseline: 3.3397x; 1.0299x over previous
#include <cuda_runtime.h>
#include <cuda_fp16.h>
#include <math.h>
#include <stdint.h>

// ---------------------------------------------------------------------------
// Problem constants: N=100000 nodes, E=1600000 edges, dims 256 -> 128 -> 128.
// ---------------------------------------------------------------------------
#define NMAX 100000
#define EMAX 1600000
#define FDIM 128
#define SCAN_TB 1024
#define NSCAN_BLOCKS ((NMAX + SCAN_TB - 1) / SCAN_TB)   // 98

// packed degree/count: [63:40] = edge count, [39:0] = weight sum in 20.20 fixed
#define DC_CNT_SHIFT 40
#define DC_W_SCALE   1048576.0f           // 2^20
#define DC_W_MASK    ((1ULL << DC_CNT_SHIFT) - 1ULL)

// Scratch (static device globals; no runtime allocation).
__device__ unsigned long long g_degcnt[NMAX];
__device__ float  g_dinv  [NMAX];
__device__ int    g_rowptr[NMAX + 1];
__device__ int    g_cursor[NMAX];
__device__ int    g_bsum  [NSCAN_BLOCKS];
__device__ int2   g_edge  [EMAX];    // CSR-by-dst: {src, coef-as-bits} per slot
__device__ __half g_h     [(size_t)NMAX * FDIM];  // GEMM output (fp16)
__device__ __half g_a     [(size_t)NMAX * FDIM];  // layer-1 activation (fp16)

// ---------------------------------------------------------------------------
// Degree/count (packed 64-bit)
// ---------------------------------------------------------------------------
__global__ void k_init(unsigned long long* dc, int n) {
    int i = blockIdx.x * blockDim.x + threadIdx.x;
    if (i < n) dc[i] = (unsigned long long)(1u << 20);   // self-loop w=1.0, cnt=0
}

__global__ void k_deg_cnt(const int* __restrict__ dst, const float* __restrict__ w,
                          unsigned long long* dc, int E) {
    int e = blockIdx.x * blockDim.x + threadIdx.x;
    if (e < E) {
        unsigned long long inc =
            (1ULL << DC_CNT_SHIFT) +
            (unsigned long long)__float2uint_rn(w[e] * DC_W_SCALE);
        atomicAdd(&dc[dst[e]], inc);
    }
}

// ---------------------------------------------------------------------------
// Device-wide exclusive scan of cnt -> rowptr (3 kernels, fully parallel).
// ---------------------------------------------------------------------------
__global__ __launch_bounds__(SCAN_TB)
void k_reduce(const unsigned long long* __restrict__ dc, int* __restrict__ bsum,
              int n) {
    __shared__ int wsum[32];
    int i = blockIdx.x * SCAN_TB + threadIdx.x;
    int v = (i < n) ? (int)(dc[i] >> DC_CNT_SHIFT) : 0;
#pragma unroll
    for (int d = 16; d > 0; d >>= 1) v += __shfl_down_sync(0xffffffffu, v, d);
    int lane = threadIdx.x & 31, wid = threadIdx.x >> 5;
    if (lane == 0) wsum[wid] = v;
    __syncthreads();
    if (wid == 0) {
        int s = wsum[lane];
#pragma unroll
        for (int d = 16; d > 0; d >>= 1) s += __shfl_down_sync(0xffffffffu, s, d);
        if (lane == 0) bsum[blockIdx.x] = s;
    }
}

__global__ __launch_bounds__(SCAN_TB)
void k_scan_sums(int* __restrict__ bsum, int nblk, int* __restrict__ rowptr,
                 int n, int E) {
    __shared__ int wsum[32];
    const int tid = threadIdx.x, lane = tid & 31, wid = tid >> 5;
    int v = (tid < nblk) ? bsum[tid] : 0;
    int x = v;
#pragma unroll
    for (int d = 1; d < 32; d <<= 1) {
        int y = __shfl_up_sync(0xffffffffu, x, d);
        if (lane >= d) x += y;
    }
    if (lane == 31) wsum[wid] = x;
    __syncthreads();
    if (wid == 0) {
        int s = wsum[lane];
#pragma unroll
        for (int d = 1; d < 32; d <<= 1) {
            int y = __shfl_up_sync(0xffffffffu, s, d);
            if (lane >= d) s += y;
        }
        wsum[lane] = s;
    }
    __syncthreads();
    int woff = wid ? wsum[wid - 1] : 0;
    if (tid < nblk) bsum[tid] = woff + x - v;   // exclusive
    if (tid == 0) rowptr[n] = E;
}

// Final pass: per-block exclusive scan + offset; writes rowptr, cursor AND dinv.
__global__ __launch_bounds__(SCAN_TB)
void k_scan_final(const unsigned long long* __restrict__ dc,
                  const int* __restrict__ bsum,
                  int* __restrict__ rowptr, int* __restrict__ cursor,
                  float* __restrict__ dinv, int n) {
    __shared__ int wsum[32];
    const int tid = threadIdx.x, lane = tid & 31, wid = tid >> 5;
    int i = blockIdx.x * SCAN_TB + tid;
    unsigned long long p = (i < n) ? dc[i] : 0ULL;
    int v = (int)(p >> DC_CNT_SHIFT);
    int x = v;
#pragma unroll
    for (int d = 1; d < 32; d <<= 1) {
        int y = __shfl_up_sync(0xffffffffu, x, d);
        if (lane >= d) x += y;
    }
    if (lane == 31) wsum[wid] = x;
    __syncthreads();
    if (wid == 0) {
        int s = wsum[lane];
#pragma unroll
        for (int d = 1; d < 32; d <<= 1) {
            int y = __shfl_up_sync(0xffffffffu, s, d);
            if (lane >= d) s += y;
        }
        wsum[lane] = s;
    }
    __syncthreads();
    int woff = wid ? wsum[wid - 1] : 0;
    if (i < n) {
        int r = bsum[blockIdx.x] + woff + x - v;
        rowptr[i] = r;
        cursor[i] = r;
        float deg = (float)(p & DC_W_MASK) * (1.0f / DC_W_SCALE);
        dinv[i] = rsqrtf(deg);
    }
}

// Fill CSR slots; packs {src, coef} into one 8B record.
__global__ void k_fill(const int* __restrict__ src, const int* __restrict__ dst,
                       const float* __restrict__ w, const float* __restrict__ dinv,
                       int* cursor, int2* __restrict__ edge, int E) {
    int e = blockIdx.x * blockDim.x + threadIdx.x;
    if (e >= E) return;
    int s = src[e], d = dst[e];
    int pos = atomicAdd(&cursor[d], 1);
    float coef = dinv[s] * w[e] * dinv[d];
    edge[pos] = make_int2(s, __float_as_int(coef));
}

// ---------------------------------------------------------------------------
// tf32 mma.sync GEMM: C[M,128] = A[M,K] @ B[K,128], epilogue stores fp16.
// A operand templated: float (layer 1) or __half (layer 2).
// CTA tile 128x128, BK=16, 8 warps, warp tile 32x64, m16n8k8, fp32 acc.
// ---------------------------------------------------------------------------
#define APITCH 20
#define BPITCH 136

__device__ __forceinline__ uint32_t f2tf32(float x) {
    uint32_t r;
    asm("cvt.rna.tf32.f32 %0, %1;" : "=r"(r) : "f"(x));
    return r;
}

__device__ __forceinline__ void mma_tf32(float* c, const uint32_t* a,
                                         uint32_t b0, uint32_t b1) {
    asm volatile(
        "mma.sync.aligned.m16n8k8.row.col.f32.tf32.tf32.f32 "
        "{%0,%1,%2,%3}, {%4,%5,%6,%7}, {%8,%9}, {%0,%1,%2,%3};"
        : "+f"(c[0]), "+f"(c[1]), "+f"(c[2]), "+f"(c[3])
        : "r"(a[0]), "r"(a[1]), "r"(a[2]), "r"(a[3]), "r"(b0), "r"(b1));
}

__device__ __forceinline__ float4 loadA4(const float* A, size_t off) {
    return *(const float4*)(A + off);
}
__device__ __forceinline__ float4 loadA4(const __half* A, size_t off) {
    uint2 raw = *(const uint2*)(A + off);             // 8B = 4 halves
    __half2 p0 = *(__half2*)&raw.x;
    __half2 p1 = *(__half2*)&raw.y;
    float2 f0 = __half22float2(p0);
    float2 f1 = __half22float2(p1);
    return make_float4(f0.x, f0.y, f1.x, f1.y);
}

template <typename AT>
__global__ __launch_bounds__(256, 2)
void k_gemm_mma(const AT* __restrict__ A, const float* __restrict__ B,
                __half* __restrict__ C, int M, int K) {
    __shared__ __align__(16) float As[2][128 * APITCH];
    __shared__ __align__(16) float Bs[2][16 * BPITCH];

    const int tid  = threadIdx.x;
    const int lane = tid & 31;
    const int wid  = tid >> 5;
    const int warp_m = wid & 3;
    const int warp_n = wid >> 2;
    const int gp = lane >> 2;
    const int tg = lane & 3;
    const int m0 = blockIdx.x * 128;

    float acc[2][8][4];
#pragma unroll
    for (int i = 0; i < 2; i++)
#pragma unroll
        for (int j = 0; j < 8; j++)
#pragma unroll
            for (int q = 0; q < 4; q++) acc[i][j][q] = 0.0f;

    float4 pa[2], pb[2];

    auto load_regs = [&](int k0) {
#pragma unroll
        for (int u = 0; u < 2; u++) {
            int idx = tid + u * 256;
            int ar  = idx >> 2;
            int aq  = idx & 3;
            pa[u] = (m0 + ar < M)
                  ? loadA4(A, (size_t)(m0 + ar) * K + k0 + aq * 4)
                  : make_float4(0.f, 0.f, 0.f, 0.f);
            int kr = idx >> 5;
            int bq = idx & 31;
            pb[u] = *(const float4*)(B + (size_t)(k0 + kr) * 128 + bq * 4);
        }
    };

    auto store_smem = [&](int buf) {
#pragma unroll
        for (int u = 0; u < 2; u++) {
            int idx = tid + u * 256;
            int ar  = idx >> 2;
            int aq  = idx & 3;
            uint32_t* d = (uint32_t*)&As[buf][ar * APITCH + aq * 4];
            d[0] = f2tf32(pa[u].x); d[1] = f2tf32(pa[u].y);
            d[2] = f2tf32(pa[u].z); d[3] = f2tf32(pa[u].w);
            int kr = idx >> 5;
            int bq = idx & 31;
            uint32_t* e = (uint32_t*)&Bs[buf][kr * BPITCH + bq * 4];
            e[0] = f2tf32(pb[u].x); e[1] = f2tf32(pb[u].y);
            e[2] = f2tf32(pb[u].z); e[3] = f2tf32(pb[u].w);
        }
    };

    const int niter = K / 16;
    load_regs(0);
    store_smem(0);

    for (int it = 0; it < niter; it++) {
        if (it + 1 < niter) load_regs((it + 1) * 16);
        __syncthreads();
        const int buf = it & 1;
        const uint32_t* as = (const uint32_t*)&As[buf][0];
        const uint32_t* bs = (const uint32_t*)&Bs[buf][0];

#pragma unroll
        for (int kk = 0; kk < 16; kk += 8) {
            uint32_t af[2][4];
#pragma unroll
            for (int i = 0; i < 2; i++) {
                int mr = warp_m * 32 + i * 16 + gp;
                af[i][0] = as[(mr    ) * APITCH + kk + tg    ];
                af[i][1] = as[(mr + 8) * APITCH + kk + tg    ];
                af[i][2] = as[(mr    ) * APITCH + kk + tg + 4];
                af[i][3] = as[(mr + 8) * APITCH + kk + tg + 4];
            }
#pragma unroll
            for (int j = 0; j < 8; j++) {
                int nb = warp_n * 64 + j * 8 + gp;
                uint32_t b0 = bs[(kk + tg    ) * BPITCH + nb];
                uint32_t b1 = bs[(kk + tg + 4) * BPITCH + nb];
#pragma unroll
                for (int i = 0; i < 2; i++)
                    mma_tf32(acc[i][j], af[i], b0, b1);
            }
        }
        if (it + 1 < niter) store_smem((it + 1) & 1);
    }

#pragma unroll
    for (int i = 0; i < 2; i++) {
        int r0 = m0 + warp_m * 32 + i * 16 + gp;
        int r1 = r0 + 8;
#pragma unroll
        for (int j = 0; j < 8; j++) {
            int col = warp_n * 64 + j * 8 + tg * 2;
            if (r0 < M)
                *(__half2*)(C + (size_t)r0 * 128 + col) =
                    __floats2half2_rn(acc[i][j][0], acc[i][j][1]);
            if (r1 < M)
                *(__half2*)(C + (size_t)r1 * 128 + col) =
                    __floats2half2_rn(acc[i][j][2], acc[i][j][3]);
        }
    }
}

// ---------------------------------------------------------------------------
// CSR aggregation + bias + erf-GELU, one warp per destination node.
// h is fp16; accumulation in fp32; output templated (fp16 mid / fp32 final).
// ---------------------------------------------------------------------------
__device__ __forceinline__ float gelu_erf(float x) {
    return 0.5f * x * (1.0f + erff(x * 0.70710678118654752440f));
}

__device__ __forceinline__ float4 load_h4(const __half* __restrict__ h,
                                          size_t row, int lane) {
    float2 raw = ((const float2*)(h + row * 128))[lane];   // 8B = 4 halves
    __half2 p0 = *(__half2*)&raw.x;
    __half2 p1 = *(__half2*)&raw.y;
    float2 f0 = __half22float2(p0);
    float2 f1 = __half22float2(p1);
    return make_float4(f0.x, f0.y, f1.x, f1.y);
}

__device__ __forceinline__ void store_out(float* out, size_t row, int lane, float4 v) {
    ((float4*)(out + row * 128))[lane] = v;
}
__device__ __forceinline__ void store_out(__half* out, size_t row, int lane, float4 v) {
    float2 packed;
    *(__half2*)&packed.x = __floats2half2_rn(v.x, v.y);
    *(__half2*)&packed.y = __floats2half2_rn(v.z, v.w);
    ((float2*)(out + row * 128))[lane] = packed;
}

template <typename OutT>
__global__ __launch_bounds__(256, 8)
void k_aggregate(const int* __restrict__ rowptr, const int2* __restrict__ edge,
                 const __half* __restrict__ h, const float* __restrict__ dinv,
                 const float* __restrict__ bias, OutT* __restrict__ out, int n) {
    int node = (blockIdx.x * blockDim.x + threadIdx.x) >> 5;
    int lane = threadIdx.x & 31;
    if (node >= n) return;

    int beg = __ldg(&rowptr[node]);
    int end = __ldg(&rowptr[node + 1]);

    float d = __ldg(&dinv[node]);
    float c = d * d;
    float4 acc = load_h4(h, (size_t)node, lane);
    acc.x *= c; acc.y *= c; acc.z *= c; acc.w *= c;

    for (int base = beg; base < end; base += 32) {
        int m = end - base;
        if (m > 32) m = 32;
        int2 e_l = (lane < m) ? __ldg(&edge[base + lane]) : make_int2(0, 0);

        int j = 0;
        for (; j + 4 <= m; j += 4) {
            int   s0 = __shfl_sync(0xffffffffu, e_l.x, j    );
            int   s1 = __shfl_sync(0xffffffffu, e_l.x, j + 1);
            int   s2 = __shfl_sync(0xffffffffu, e_l.x, j + 2);
            int   s3 = __shfl_sync(0xffffffffu, e_l.x, j + 3);
            float w0 = __int_as_float(__shfl_sync(0xffffffffu, e_l.y, j    ));
            float w1 = __int_as_float(__shfl_sync(0xffffffffu, e_l.y, j + 1));
            float w2 = __int_as_float(__shfl_sync(0xffffffffu, e_l.y, j + 2));
            float w3 = __int_as_float(__shfl_sync(0xffffffffu, e_l.y, j + 3));
            float4 v0 = load_h4(h, (size_t)s0, lane);
            float4 v1 = load_h4(h, (size_t)s1, lane);
            float4 v2 = load_h4(h, (size_t)s2, lane);
            float4 v3 = load_h4(h, (size_t)s3, lane);
            acc.x = fmaf(v0.x, w0, acc.x); acc.y = fmaf(v0.y, w0, acc.y);
            acc.z = fmaf(v0.z, w0, acc.z); acc.w = fmaf(v0.w, w0, acc.w);
            acc.x = fmaf(v1.x, w1, acc.x); acc.y = fmaf(v1.y, w1, acc.y);
            acc.z = fmaf(v1.z, w1, acc.z); acc.w = fmaf(v1.w, w1, acc.w);
            acc.x = fmaf(v2.x, w2, acc.x); acc.y = fmaf(v2.y, w2, acc.y);
            acc.z = fmaf(v2.z, w2, acc.z); acc.w = fmaf(v2.w, w2, acc.w);
            acc.x = fmaf(v3.x, w3, acc.x); acc.y = fmaf(v3.y, w3, acc.y);
            acc.z = fmaf(v3.z, w3, acc.z); acc.w = fmaf(v3.w, w3, acc.w);
        }
        for (; j < m; j++) {
            int   s = __shfl_sync(0xffffffffu, e_l.x, j);
            float w = __int_as_float(__shfl_sync(0xffffffffu, e_l.y, j));
            float4 v = load_h4(h, (size_t)s, lane);
            acc.x = fmaf(v.x, w, acc.x);
            acc.y = fmaf(v.y, w, acc.y);
            acc.z = fmaf(v.z, w, acc.z);
            acc.w = fmaf(v.w, w, acc.w);
        }
    }

    float4 bb = ((const float4*)bias)[lane];
    acc.x = gelu_erf(acc.x + bb.x);
    acc.y = gelu_erf(acc.y + bb.y);
    acc.z = gelu_erf(acc.z + bb.z);
    acc.w = gelu_erf(acc.w + bb.w);
    store_out(out, (size_t)node, lane, acc);
}

// ---------------------------------------------------------------------------
// Launch. Graph topology:
//   default stream:  [fork] GEMM1 ----------------[join] agg1  GEMM2  agg2
//   side stream s2:  [fork] init degcnt reduce scan scan+dinv fill [join]
// ---------------------------------------------------------------------------
extern "C" void kernel_launch(void* const* d_in, const int* in_sizes, int n_in,
                              void* d_out, int out_size) {
    const float* x  = (const float*)d_in[0];
    const int*   ei = (const int*)  d_in[1];
    const float* ew = (const float*)d_in[2];
    const float* W1 = (const float*)d_in[3];
    const float* b1 = (const float*)d_in[4];
    const float* W2 = (const float*)d_in[5];
    const float* b2 = (const float*)d_in[6];
    float* out = (float*)d_out;

    const int n  = out_size / FDIM;       // 100000
    const int K1 = in_sizes[0] / n;       // 256
    const int E  = in_sizes[2];           // 1600000
    const int* src = ei;
    const int* dst = ei + E;

    unsigned long long* dc;
    float* dinv;
    __half *h, *a;
    int *rowptr, *cursor, *bsum;
    int2* edge;
    cudaGetSymbolAddress((void**)&dc,     g_degcnt);
    cudaGetSymbolAddress((void**)&dinv,   g_dinv);
    cudaGetSymbolAddress((void**)&rowptr, g_rowptr);
    cudaGetSymbolAddress((void**)&cursor, g_cursor);
    cudaGetSymbolAddress((void**)&edge,   g_edge);
    cudaGetSymbolAddress((void**)&h,      g_h);
    cudaGetSymbolAddress((void**)&a,      g_a);
    cudaGetSymbolAddress((void**)&bsum,   g_bsum);

    const int TB = 256;
    const int nblk = (n + SCAN_TB - 1) / SCAN_TB;
    dim3 gn((n + TB - 1) / TB);
    dim3 ge((E + TB - 1) / TB);
    dim3 gagg(((size_t)n * 32 + TB - 1) / TB);
    dim3 ggemm((n + 127) / 128);

    cudaStream_t s2;
    cudaEvent_t evFork, evJoin;
    cudaStreamCreateWithFlags(&s2, cudaStreamNonBlocking);
    cudaEventCreateWithFlags(&evFork, cudaEventDisableTiming);
    cudaEventCreateWithFlags(&evJoin, cudaEventDisableTiming);

    cudaEventRecord(evFork, 0);
    cudaStreamWaitEvent(s2, evFork, 0);

    // --- side stream: CSR-by-dst build + normalization (5 kernels) ---
    k_init      <<<gn, TB, 0, s2>>>(dc, n);
    k_deg_cnt   <<<ge, TB, 0, s2>>>(dst, ew, dc, E);
    k_reduce    <<<nblk, SCAN_TB, 0, s2>>>(dc, bsum, n);
    k_scan_sums <<<1, SCAN_TB, 0, s2>>>(bsum, nblk, rowptr, n, E);
    k_scan_final<<<nblk, SCAN_TB, 0, s2>>>(dc, bsum, rowptr, cursor, dinv, n);
    k_fill      <<<ge, TB, 0, s2>>>(src, dst, ew, dinv, cursor, edge, E);
    cudaEventRecord(evJoin, s2);

    // --- default stream: GEMM1 runs concurrently with the CSR build ---
    k_gemm_mma<float><<<ggemm, 256>>>(x, W1, h, n, K1);

    cudaStreamWaitEvent(0, evJoin, 0);

    // --- layer 1 aggregate (fp16 out), layer 2 GEMM (fp16 A), final agg ---
    k_aggregate<__half><<<gagg, TB>>>(rowptr, edge, h, dinv, b1, a, n);
    k_gemm_mma<__half><<<ggemm, 256>>>(a, W2, h, n, FDIM);
    k_aggregate<float> <<<gagg, TB>>>(rowptr, edge, h, dinv, b2, out, n);
}

// round 11
// speedup vs baseline: 3.3444x; 1.0014x over previous
#include <cuda_runtime.h>
#include <cuda_fp16.h>
#include <math.h>
#include <stdint.h>

// ---------------------------------------------------------------------------
// Problem constants: N=100000 nodes, E=1600000 edges, dims 256 -> 128 -> 128.
// ---------------------------------------------------------------------------
#define NMAX 100000
#define EMAX 1600000
#define FDIM 128
#define SCAN_TB 1024
#define NSCAN_BLOCKS ((NMAX + SCAN_TB - 1) / SCAN_TB)   // 98

// packed degree/count: [63:40] = edge count, [39:0] = weight sum in 20.20 fixed
#define DC_CNT_SHIFT 40
#define DC_W_SCALE   1048576.0f           // 2^20
#define DC_W_MASK    ((1ULL << DC_CNT_SHIFT) - 1ULL)

// Scratch (static device globals; no runtime allocation).
__device__ unsigned long long g_degcnt[NMAX];
__device__ unsigned long long g_bstate[NSCAN_BLOCKS];  // lookback: (status<<32)|val
__device__ float  g_dinv  [NMAX];
__device__ int    g_rowptr[NMAX + 1];
__device__ int    g_cursor[NMAX];
__device__ int2   g_edge  [EMAX];    // CSR-by-dst: {src, coef-as-bits} per slot
__device__ __half g_h     [(size_t)NMAX * FDIM];  // GEMM output (fp16)
__device__ __half g_a     [(size_t)NMAX * FDIM];  // layer-1 activation (fp16)

// ---------------------------------------------------------------------------
// Init: packed deg/cnt to self-loop, zero lookback state.
// ---------------------------------------------------------------------------
__global__ void k_init(unsigned long long* dc, unsigned long long* bstate, int n) {
    int i = blockIdx.x * blockDim.x + threadIdx.x;
    if (i < n) dc[i] = (unsigned long long)(1u << 20);   // self-loop w=1.0, cnt=0
    if (i < NSCAN_BLOCKS) bstate[i] = 0ULL;
}

__global__ void k_deg_cnt(const int* __restrict__ dst, const float* __restrict__ w,
                          unsigned long long* dc, int E) {
    int e = blockIdx.x * blockDim.x + threadIdx.x;
    if (e < E) {
        unsigned long long inc =
            (1ULL << DC_CNT_SHIFT) +
            (unsigned long long)__float2uint_rn(w[e] * DC_W_SCALE);
        atomicAdd(&dc[dst[e]], inc);
    }
}

// ---------------------------------------------------------------------------
// Single-pass decoupled-lookback exclusive scan over counts.
// Writes rowptr, cursor, dinv, and rowptr[n]=E. One kernel, 98 blocks —
// all co-resident on 148 SMs, so the lookback spin cannot deadlock.
// Status: 0=invalid, 1=block aggregate ready, 2=inclusive prefix ready.
// Value+status share one 64-bit word -> single atomic, no fences needed.
// ---------------------------------------------------------------------------
__global__ __launch_bounds__(SCAN_TB)
void k_scan_onepass(const unsigned long long* __restrict__ dc,
                    unsigned long long* __restrict__ bstate,
                    int* __restrict__ rowptr, int* __restrict__ cursor,
                    float* __restrict__ dinv, int n, int E) {
    __shared__ int wsum[32];
    __shared__ int s_prefix;
    const int tid = threadIdx.x, lane = tid & 31, wid = tid >> 5;
    const int bid = blockIdx.x;
    int i = bid * SCAN_TB + tid;

    unsigned long long p = (i < n) ? dc[i] : 0ULL;
    int v = (int)(p >> DC_CNT_SHIFT);
    int x = v;
#pragma unroll
    for (int d = 1; d < 32; d <<= 1) {
        int y = __shfl_up_sync(0xffffffffu, x, d);
        if (lane >= d) x += y;
    }
    if (lane == 31) wsum[wid] = x;
    __syncthreads();
    if (wid == 0) {
        int s = wsum[lane];
#pragma unroll
        for (int d = 1; d < 32; d <<= 1) {
            int y = __shfl_up_sync(0xffffffffu, s, d);
            if (lane >= d) s += y;
        }
        wsum[lane] = s;
    }
    __syncthreads();
    int woff = wid ? wsum[wid - 1] : 0;
    int local_excl = woff + x - v;
    int btotal = wsum[31];

    // decoupled lookback (thread 0)
    if (tid == 0) {
        int prefix = 0;
        if (bid == 0) {
            atomicExch(&bstate[0], (2ULL << 32) | (unsigned)btotal);
        } else {
            atomicExch(&bstate[bid], (1ULL << 32) | (unsigned)btotal);
            for (int j = bid - 1; j >= 0; ) {
                unsigned long long s;
                do { s = atomicAdd(&bstate[j], 0ULL); } while ((s >> 32) == 0);
                prefix += (int)(unsigned)s;
                if ((s >> 32) == 2ULL) break;
                j--;
            }
            atomicExch(&bstate[bid], (2ULL << 32) | (unsigned)(prefix + btotal));
        }
        s_prefix = prefix;
    }
    __syncthreads();

    if (i < n) {
        int r = s_prefix + local_excl;
        rowptr[i] = r;
        cursor[i] = r;
        float deg = (float)(p & DC_W_MASK) * (1.0f / DC_W_SCALE);
        dinv[i] = rsqrtf(deg);
    }
    if (bid == gridDim.x - 1 && tid == 0) rowptr[n] = E;
}

// Fill CSR slots; packs {src, coef} into one 8B record.
__global__ void k_fill(const int* __restrict__ src, const int* __restrict__ dst,
                       const float* __restrict__ w, const float* __restrict__ dinv,
                       int* cursor, int2* __restrict__ edge, int E) {
    int e = blockIdx.x * blockDim.x + threadIdx.x;
    if (e >= E) return;
    int s = src[e], d = dst[e];
    int pos = atomicAdd(&cursor[d], 1);
    float coef = dinv[s] * w[e] * dinv[d];
    edge[pos] = make_int2(s, __float_as_int(coef));
}

// ---------------------------------------------------------------------------
// tf32 mma.sync GEMM: C[M,128] = A[M,K] @ B[K,128], epilogue stores fp16.
// A operand templated: float (layer 1) or __half (layer 2).
// CTA tile 128x128, BK=16, 8 warps, warp tile 32x64, m16n8k8, fp32 acc.
// ---------------------------------------------------------------------------
#define APITCH 20
#define BPITCH 136

__device__ __forceinline__ uint32_t f2tf32(float x) {
    uint32_t r;
    asm("cvt.rna.tf32.f32 %0, %1;" : "=r"(r) : "f"(x));
    return r;
}

__device__ __forceinline__ void mma_tf32(float* c, const uint32_t* a,
                                         uint32_t b0, uint32_t b1) {
    asm volatile(
        "mma.sync.aligned.m16n8k8.row.col.f32.tf32.tf32.f32 "
        "{%0,%1,%2,%3}, {%4,%5,%6,%7}, {%8,%9}, {%0,%1,%2,%3};"
        : "+f"(c[0]), "+f"(c[1]), "+f"(c[2]), "+f"(c[3])
        : "r"(a[0]), "r"(a[1]), "r"(a[2]), "r"(a[3]), "r"(b0), "r"(b1));
}

__device__ __forceinline__ float4 loadA4(const float* A, size_t off) {
    return *(const float4*)(A + off);
}
__device__ __forceinline__ float4 loadA4(const __half* A, size_t off) {
    uint2 raw = *(const uint2*)(A + off);             // 8B = 4 halves
    __half2 p0 = *(__half2*)&raw.x;
    __half2 p1 = *(__half2*)&raw.y;
    float2 f0 = __half22float2(p0);
    float2 f1 = __half22float2(p1);
    return make_float4(f0.x, f0.y, f1.x, f1.y);
}

template <typename AT>
__global__ __launch_bounds__(256, 2)
void k_gemm_mma(const AT* __restrict__ A, const float* __restrict__ B,
                __half* __restrict__ C, int M, int K) {
    __shared__ __align__(16) float As[2][128 * APITCH];
    __shared__ __align__(16) float Bs[2][16 * BPITCH];

    const int tid  = threadIdx.x;
    const int lane = tid & 31;
    const int wid  = tid >> 5;
    const int warp_m = wid & 3;
    const int warp_n = wid >> 2;
    const int gp = lane >> 2;
    const int tg = lane & 3;
    const int m0 = blockIdx.x * 128;

    float acc[2][8][4];
#pragma unroll
    for (int i = 0; i < 2; i++)
#pragma unroll
        for (int j = 0; j < 8; j++)
#pragma unroll
            for (int q = 0; q < 4; q++) acc[i][j][q] = 0.0f;

    float4 pa[2], pb[2];

    auto load_regs = [&](int k0) {
#pragma unroll
        for (int u = 0; u < 2; u++) {
            int idx = tid + u * 256;
            int ar  = idx >> 2;
            int aq  = idx & 3;
            pa[u] = (m0 + ar < M)
                  ? loadA4(A, (size_t)(m0 + ar) * K + k0 + aq * 4)
                  : make_float4(0.f, 0.f, 0.f, 0.f);
            int kr = idx >> 5;
            int bq = idx & 31;
            pb[u] = *(const float4*)(B + (size_t)(k0 + kr) * 128 + bq * 4);
        }
    };

    auto store_smem = [&](int buf) {
#pragma unroll
        for (int u = 0; u < 2; u++) {
            int idx = tid + u * 256;
            int ar  = idx >> 2;
            int aq  = idx & 3;
            uint32_t* d = (uint32_t*)&As[buf][ar * APITCH + aq * 4];
            d[0] = f2tf32(pa[u].x); d[1] = f2tf32(pa[u].y);
            d[2] = f2tf32(pa[u].z); d[3] = f2tf32(pa[u].w);
            int kr = idx >> 5;
            int bq = idx & 31;
            uint32_t* e = (uint32_t*)&Bs[buf][kr * BPITCH + bq * 4];
            e[0] = f2tf32(pb[u].x); e[1] = f2tf32(pb[u].y);
            e[2] = f2tf32(pb[u].z); e[3] = f2tf32(pb[u].w);
        }
    };

    const int niter = K / 16;
    load_regs(0);
    store_smem(0);

    for (int it = 0; it < niter; it++) {
        if (it + 1 < niter) load_regs((it + 1) * 16);
        __syncthreads();
        const int buf = it & 1;
        const uint32_t* as = (const uint32_t*)&As[buf][0];
        const uint32_t* bs = (const uint32_t*)&Bs[buf][0];

#pragma unroll
        for (int kk = 0; kk < 16; kk += 8) {
            uint32_t af[2][4];
#pragma unroll
            for (int i = 0; i < 2; i++) {
                int mr = warp_m * 32 + i * 16 + gp;
                af[i][0] = as[(mr    ) * APITCH + kk + tg    ];
                af[i][1] = as[(mr + 8) * APITCH + kk + tg    ];
                af[i][2] = as[(mr    ) * APITCH + kk + tg + 4];
                af[i][3] = as[(mr + 8) * APITCH + kk + tg + 4];
            }
#pragma unroll
            for (int j = 0; j < 8; j++) {
                int nb = warp_n * 64 + j * 8 + gp;
                uint32_t b0 = bs[(kk + tg    ) * BPITCH + nb];
                uint32_t b1 = bs[(kk + tg + 4) * BPITCH + nb];
#pragma unroll
                for (int i = 0; i < 2; i++)
                    mma_tf32(acc[i][j], af[i], b0, b1);
            }
        }
        if (it + 1 < niter) store_smem((it + 1) & 1);
    }

#pragma unroll
    for (int i = 0; i < 2; i++) {
        int r0 = m0 + warp_m * 32 + i * 16 + gp;
        int r1 = r0 + 8;
#pragma unroll
        for (int j = 0; j < 8; j++) {
            int col = warp_n * 64 + j * 8 + tg * 2;
            if (r0 < M)
                *(__half2*)(C + (size_t)r0 * 128 + col) =
                    __floats2half2_rn(acc[i][j][0], acc[i][j][1]);
            if (r1 < M)
                *(__half2*)(C + (size_t)r1 * 128 + col) =
                    __floats2half2_rn(acc[i][j][2], acc[i][j][3]);
        }
    }
}

// ---------------------------------------------------------------------------
// CSR aggregation + bias + erf-GELU, one warp per destination node.
// h is fp16; accumulation in fp32; output templated (fp16 mid / fp32 final).
// ---------------------------------------------------------------------------
__device__ __forceinline__ float gelu_erf(float x) {
    return 0.5f * x * (1.0f + erff(x * 0.70710678118654752440f));
}

__device__ __forceinline__ float4 load_h4(const __half* __restrict__ h,
                                          size_t row, int lane) {
    float2 raw = ((const float2*)(h + row * 128))[lane];   // 8B = 4 halves
    __half2 p0 = *(__half2*)&raw.x;
    __half2 p1 = *(__half2*)&raw.y;
    float2 f0 = __half22float2(p0);
    float2 f1 = __half22float2(p1);
    return make_float4(f0.x, f0.y, f1.x, f1.y);
}

__device__ __forceinline__ void store_out(float* out, size_t row, int lane, float4 v) {
    ((float4*)(out + row * 128))[lane] = v;
}
__device__ __forceinline__ void store_out(__half* out, size_t row, int lane, float4 v) {
    float2 packed;
    *(__half2*)&packed.x = __floats2half2_rn(v.x, v.y);
    *(__half2*)&packed.y = __floats2half2_rn(v.z, v.w);
    ((float2*)(out + row * 128))[lane] = packed;
}

template <typename OutT>
__global__ __launch_bounds__(256, 8)
void k_aggregate(const int* __restrict__ rowptr, const int2* __restrict__ edge,
                 const __half* __restrict__ h, const float* __restrict__ dinv,
                 const float* __restrict__ bias, OutT* __restrict__ out, int n) {
    int node = (blockIdx.x * blockDim.x + threadIdx.x) >> 5;
    int lane = threadIdx.x & 31;
    if (node >= n) return;

    int beg = __ldg(&rowptr[node]);
    int end = __ldg(&rowptr[node + 1]);

    float d = __ldg(&dinv[node]);
    float c = d * d;
    float4 acc = load_h4(h, (size_t)node, lane);
    acc.x *= c; acc.y *= c; acc.z *= c; acc.w *= c;

    for (int base = beg; base < end; base += 32) {
        int m = end - base;
        if (m > 32) m = 32;
        int2 e_l = (lane < m) ? __ldg(&edge[base + lane]) : make_int2(0, 0);

        int j = 0;
        for (; j + 4 <= m; j += 4) {
            int   s0 = __shfl_sync(0xffffffffu, e_l.x, j    );
            int   s1 = __shfl_sync(0xffffffffu, e_l.x, j + 1);
            int   s2 = __shfl_sync(0xffffffffu, e_l.x, j + 2);
            int   s3 = __shfl_sync(0xffffffffu, e_l.x, j + 3);
            float w0 = __int_as_float(__shfl_sync(0xffffffffu, e_l.y, j    ));
            float w1 = __int_as_float(__shfl_sync(0xffffffffu, e_l.y, j + 1));
            float w2 = __int_as_float(__shfl_sync(0xffffffffu, e_l.y, j + 2));
            float w3 = __int_as_float(__shfl_sync(0xffffffffu, e_l.y, j + 3));
            float4 v0 = load_h4(h, (size_t)s0, lane);
            float4 v1 = load_h4(h, (size_t)s1, lane);
            float4 v2 = load_h4(h, (size_t)s2, lane);
            float4 v3 = load_h4(h, (size_t)s3, lane);
            acc.x = fmaf(v0.x, w0, acc.x); acc.y = fmaf(v0.y, w0, acc.y);
            acc.z = fmaf(v0.z, w0, acc.z); acc.w = fmaf(v0.w, w0, acc.w);
            acc.x = fmaf(v1.x, w1, acc.x); acc.y = fmaf(v1.y, w1, acc.y);
            acc.z = fmaf(v1.z, w1, acc.z); acc.w = fmaf(v1.w, w1, acc.w);
            acc.x = fmaf(v2.x, w2, acc.x); acc.y = fmaf(v2.y, w2, acc.y);
            acc.z = fmaf(v2.z, w2, acc.z); acc.w = fmaf(v2.w, w2, acc.w);
            acc.x = fmaf(v3.x, w3, acc.x); acc.y = fmaf(v3.y, w3, acc.y);
            acc.z = fmaf(v3.z, w3, acc.z); acc.w = fmaf(v3.w, w3, acc.w);
        }
        for (; j < m; j++) {
            int   s = __shfl_sync(0xffffffffu, e_l.x, j);
            float w = __int_as_float(__shfl_sync(0xffffffffu, e_l.y, j));
            float4 v = load_h4(h, (size_t)s, lane);
            acc.x = fmaf(v.x, w, acc.x);
            acc.y = fmaf(v.y, w, acc.y);
            acc.z = fmaf(v.z, w, acc.z);
            acc.w = fmaf(v.w, w, acc.w);
        }
    }

    float4 bb = ((const float4*)bias)[lane];
    acc.x = gelu_erf(acc.x + bb.x);
    acc.y = gelu_erf(acc.y + bb.y);
    acc.z = gelu_erf(acc.z + bb.z);
    acc.w = gelu_erf(acc.w + bb.w);
    store_out(out, (size_t)node, lane, acc);
}

// ---------------------------------------------------------------------------
// Launch. Graph topology:
//   default stream:  [fork] GEMM1 --------------[join] agg1  GEMM2  agg2
//   side stream s2:  [fork] init degcnt scan1 fill [join]
// ---------------------------------------------------------------------------
extern "C" void kernel_launch(void* const* d_in, const int* in_sizes, int n_in,
                              void* d_out, int out_size) {
    const float* x  = (const float*)d_in[0];
    const int*   ei = (const int*)  d_in[1];
    const float* ew = (const float*)d_in[2];
    const float* W1 = (const float*)d_in[3];
    const float* b1 = (const float*)d_in[4];
    const float* W2 = (const float*)d_in[5];
    const float* b2 = (const float*)d_in[6];
    float* out = (float*)d_out;

    const int n  = out_size / FDIM;       // 100000
    const int K1 = in_sizes[0] / n;       // 256
    const int E  = in_sizes[2];           // 1600000
    const int* src = ei;
    const int* dst = ei + E;

    unsigned long long *dc, *bstate;
    float* dinv;
    __half *h, *a;
    int *rowptr, *cursor;
    int2* edge;
    cudaGetSymbolAddress((void**)&dc,     g_degcnt);
    cudaGetSymbolAddress((void**)&bstate, g_bstate);
    cudaGetSymbolAddress((void**)&dinv,   g_dinv);
    cudaGetSymbolAddress((void**)&rowptr, g_rowptr);
    cudaGetSymbolAddress((void**)&cursor, g_cursor);
    cudaGetSymbolAddress((void**)&edge,   g_edge);
    cudaGetSymbolAddress((void**)&h,      g_h);
    cudaGetSymbolAddress((void**)&a,      g_a);

    const int TB = 256;
    const int nblk = (n + SCAN_TB - 1) / SCAN_TB;
    dim3 gn((n + TB - 1) / TB);
    dim3 ge((E + TB - 1) / TB);
    dim3 gagg(((size_t)n * 32 + TB - 1) / TB);
    dim3 ggemm((n + 127) / 128);

    cudaStream_t s2;
    cudaEvent_t evFork, evJoin;
    cudaStreamCreateWithFlags(&s2, cudaStreamNonBlocking);
    cudaEventCreateWithFlags(&evFork, cudaEventDisableTiming);
    cudaEventCreateWithFlags(&evJoin, cudaEventDisableTiming);

    cudaEventRecord(evFork, 0);
    cudaStreamWaitEvent(s2, evFork, 0);

    // --- side stream: CSR-by-dst build + normalization (4 kernels) ---
    k_init        <<<gn, TB, 0, s2>>>(dc, bstate, n);
    k_deg_cnt     <<<ge, TB, 0, s2>>>(dst, ew, dc, E);
    k_scan_onepass<<<nblk, SCAN_TB, 0, s2>>>(dc, bstate, rowptr, cursor, dinv, n, E);
    k_fill        <<<ge, TB, 0, s2>>>(src, dst, ew, dinv, cursor, edge, E);
    cudaEventRecord(evJoin, s2);

    // --- default stream: GEMM1 runs concurrently with the CSR build ---
    k_gemm_mma<float><<<ggemm, 256>>>(x, W1, h, n, K1);

    cudaStreamWaitEvent(0, evJoin, 0);

    // --- layer 1 aggregate (fp16 out), layer 2 GEMM (fp16 A), final agg ---
    k_aggregate<__half><<<gagg, TB>>>(rowptr, edge, h, dinv, b1, a, n);
    k_gemm_mma<__half><<<ggemm, 256>>>(a, W2, h, n, FDIM);
    k_aggregate<float> <<<gagg, TB>>>(rowptr, edge, h, dinv, b2, out, n);
}